// round 10
// baseline (speedup 1.0000x reference)
#include <cuda_runtime.h>
#include <cuda_fp16.h>
#include <cstdint>

#define NTOK 2560
#define EDIM 512
#define NHEAD 8
#define HDIM 64
#define FFD 2048
#define VOC 32000
#define SEQ 80
#define NLAYER 4
#define BK 64

// ---------------- device scratch ----------------
__device__ float g_x[NTOK * EDIM];
__device__ float g_qkv[NTOK * 3 * EDIM];
__device__ float g_t512[3 * NTOK * EDIM];
__device__ float g_c[NLAYER * EDIM];
__device__ __half g_xh[NTOK * EDIM];
__device__ __half g_t512h[NTOK * EDIM];
__device__ __half g_h1h[NTOK * FFD];
__device__ __half g_wsain[NLAYER * 3 * EDIM * EDIM];
__device__ __half g_wsaout[NLAYER * EDIM * EDIM];
__device__ __half g_wff1[NLAYER * FFD * EDIM];
__device__ __half g_wff2[NLAYER * EDIM * FFD];
__device__ __half g_wout[(size_t)VOC * EDIM];

// ---------------- PTX helpers ----------------
__device__ __forceinline__ uint32_t smem_u32(const void* p) {
    uint32_t a;
    asm("{ .reg .u64 t; cvta.to.shared.u64 t, %1; cvt.u32.u64 %0, t; }" : "=r"(a) : "l"(p));
    return a;
}
__device__ __forceinline__ void cp16(uint32_t dst, const void* src) {
    asm volatile("cp.async.cg.shared.global [%0], [%1], 16;\n" :: "r"(dst), "l"(src));
}
__device__ __forceinline__ void cp_commit() { asm volatile("cp.async.commit_group;\n" ::: "memory"); }
template <int N>
__device__ __forceinline__ void cp_wait() { asm volatile("cp.async.wait_group %0;\n" :: "n"(N) : "memory"); }

__device__ __forceinline__ void ldsm4(uint32_t r[4], uint32_t addr) {
    asm volatile("ldmatrix.sync.aligned.m8n8.x4.shared.b16 {%0,%1,%2,%3},[%4];\n"
                 : "=r"(r[0]), "=r"(r[1]), "=r"(r[2]), "=r"(r[3]) : "r"(addr));
}
__device__ __forceinline__ void mma16816(float d[4], const uint32_t a[4], const uint32_t b[2]) {
    asm volatile(
        "mma.sync.aligned.m16n8k16.row.col.f32.f16.f16.f32 "
        "{%0,%1,%2,%3},{%4,%5,%6,%7},{%8,%9},{%0,%1,%2,%3};\n"
        : "+f"(d[0]), "+f"(d[1]), "+f"(d[2]), "+f"(d[3])
        : "r"(a[0]), "r"(a[1]), "r"(a[2]), "r"(a[3]), "r"(b[0]), "r"(b[1]));
}
__device__ __forceinline__ uint32_t swz(uint32_t off) { return off ^ ((off >> 3) & 0x70); }

// ---------------- pipelined fp16 HMMA GEMM, 128x128 CTA, split-K (layer GEMMs) ----
#define BMt 128
#define BNt 128
#define NTN 8
#define NSTG 3
#define STB ((BMt + BNt) * 128)
#define SMEM_G (NSTG * STB)

__global__ void __launch_bounds__(256, 2) gemm_k(
    const __half* __restrict__ A, const __half* __restrict__ B,
    const float* __restrict__ bias, float* __restrict__ C, __half* __restrict__ Ch,
    int M, int N, int ldk, int ksp, int K, size_t csplit, int dorelu)
{
    extern __shared__ __align__(16) char sm[];
    const int tid = threadIdx.x, lane = tid & 31, warp = tid >> 5;
    const int bm = blockIdx.x * BMt, bn = blockIdx.y * BNt;
    const int z = blockIdx.z;
    const int k0 = z * ksp;
    const int klen = min(ksp, K - k0);
    const int S = klen / BK;
    const int wm = (warp & 3) * 32, wn = (warp >> 2) * (NTN * 8);
    const uint32_t smem0 = smem_u32(sm);

    float acc[2][NTN][4] = {};

    auto load_stage = [&](int st, int kabs) {
        uint32_t b0 = smem0 + (uint32_t)st * STB;
#pragma unroll
        for (int i = tid; i < (BMt + BNt) * 8; i += 256) {
            int r = i >> 3, cb = (i & 7) * 16;
            bool isA = r < BMt;
            int rr = isA ? r : r - BMt;
            uint32_t dst = b0 + (isA ? 0u : (uint32_t)BMt * 128) + swz(rr * 128 + cb);
            const char* p = isA ? (const char*)(A + (size_t)(bm + rr) * ldk + kabs) + cb
                                : (const char*)(B + (size_t)(bn + rr) * ldk + kabs) + cb;
            cp16(dst, p);
        }
    };

#pragma unroll
    for (int s = 0; s < NSTG - 1; s++) {
        if (s < S) load_stage(s, k0 + s * BK);
        cp_commit();
    }

    const int lrow = lane & 7, seg = lane >> 3;
    for (int s = 0; s < S; s++) {
        cp_wait<NSTG - 2>();
        __syncthreads();
        if (s + NSTG - 1 < S) load_stage((s + NSTG - 1) % NSTG, k0 + (s + NSTG - 1) * BK);
        cp_commit();

        uint32_t b0 = smem0 + (uint32_t)(s % NSTG) * STB;
        uint32_t aA = b0, bB = b0 + (uint32_t)BMt * 128;

        uint32_t af[2][2][4];
#pragma unroll
        for (int mt = 0; mt < 2; mt++)
            ldsm4(af[0][mt], aA + swz((wm + mt * 16 + (lane & 15)) * 128 + (lane >> 4) * 16));

#pragma unroll
        for (int kc = 0; kc < 4; kc++) {
            const int kb = kc * 32;
            const int cur = kc & 1, nxt = cur ^ 1;
            uint32_t bfr[NTN][2];
#pragma unroll
            for (int nt = 0; nt < NTN; nt += 2) {
                uint32_t t4[4];
                ldsm4(t4, bB + swz((wn + (nt + (seg >> 1)) * 8 + lrow) * 128 +
                                   kb + (seg & 1) * 16));
                bfr[nt][0] = t4[0]; bfr[nt][1] = t4[1];
                bfr[nt + 1][0] = t4[2]; bfr[nt + 1][1] = t4[3];
            }
            if (kc < 3) {
                const int kb2 = kb + 32;
#pragma unroll
                for (int mt = 0; mt < 2; mt++)
                    ldsm4(af[nxt][mt], aA + swz((wm + mt * 16 + (lane & 15)) * 128 +
                                                kb2 + (lane >> 4) * 16));
            }
#pragma unroll
            for (int mt = 0; mt < 2; mt++)
#pragma unroll
                for (int nt = 0; nt < NTN; nt++)
                    mma16816(acc[mt][nt], af[cur][mt], bfr[nt]);
        }
    }

    float* Cz = C ? C + (size_t)z * csplit : nullptr;
#pragma unroll
    for (int mt = 0; mt < 2; mt++) {
#pragma unroll
        for (int nt = 0; nt < NTN; nt++) {
            int row = bm + wm + mt * 16 + (lane >> 2);
            int col = bn + wn + nt * 8 + (lane & 3) * 2;
            float b0 = (z == 0) ? bias[col] : 0.f;
            float b1 = (z == 0) ? bias[col + 1] : 0.f;
            float v0 = acc[mt][nt][0] + b0, v1 = acc[mt][nt][1] + b1;
            float v2 = acc[mt][nt][2] + b0, v3 = acc[mt][nt][3] + b1;
            if (dorelu) {
                v0 = fmaxf(v0, 0.f); v1 = fmaxf(v1, 0.f);
                v2 = fmaxf(v2, 0.f); v3 = fmaxf(v3, 0.f);
            }
            if (Cz) {
                *(float2*)&Cz[(size_t)row * N + col] = make_float2(v0, v1);
                *(float2*)&Cz[(size_t)(row + 8) * N + col] = make_float2(v2, v3);
            }
            if (Ch) {
                *(__half2*)&Ch[(size_t)row * N + col] = __floats2half2_rn(v0, v1);
                *(__half2*)&Ch[(size_t)(row + 8) * N + col] = __floats2half2_rn(v2, v3);
            }
        }
    }
}

// ---------------- FAT head GEMM: 128x256 CTA, 8 warps, warp tile 64x64 ----------
// Halves smem traffic per MAC vs 128x128: tensor pipe becomes the sole binding pipe.
#define FM 128
#define FN 256
#define FSTB ((FM + FN) * 128)
#define SMEM_F (NSTG * FSTB)

__global__ void __launch_bounds__(256, 1) gemm_fat(
    const __half* __restrict__ A, const __half* __restrict__ B,
    const float* __restrict__ bias, float* __restrict__ C, int M, int N, int K)
{
    extern __shared__ __align__(16) char sm[];
    const int tid = threadIdx.x, lane = tid & 31, warp = tid >> 5;
    const int bm = blockIdx.x * FM, bn = blockIdx.y * FN;
    const int wm = (warp & 1) * 64, wn = (warp >> 1) * 64;
    const uint32_t smem0 = smem_u32(sm);
    const int S = K / BK;

    float acc[4][8][4] = {};

    auto load_stage = [&](int st, int kabs) {
        uint32_t b0 = smem0 + (uint32_t)st * FSTB;
#pragma unroll
        for (int i = tid; i < (FM + FN) * 8; i += 256) {
            int r = i >> 3, cb = (i & 7) * 16;
            bool isA = r < FM;
            int rr = isA ? r : r - FM;
            uint32_t dst = b0 + (isA ? 0u : (uint32_t)FM * 128) + swz(rr * 128 + cb);
            const char* p = isA ? (const char*)(A + (size_t)(bm + rr) * K + kabs) + cb
                                : (const char*)(B + (size_t)(bn + rr) * K + kabs) + cb;
            cp16(dst, p);
        }
    };

#pragma unroll
    for (int s = 0; s < NSTG - 1; s++) {
        if (s < S) load_stage(s, s * BK);
        cp_commit();
    }

    const int lrow = lane & 7, seg = lane >> 3;
    for (int s = 0; s < S; s++) {
        cp_wait<NSTG - 2>();
        __syncthreads();
        if (s + NSTG - 1 < S) load_stage((s + NSTG - 1) % NSTG, (s + NSTG - 1) * BK);
        cp_commit();

        uint32_t b0 = smem0 + (uint32_t)(s % NSTG) * FSTB;
        uint32_t aA = b0, bB = b0 + (uint32_t)FM * 128;
#pragma unroll
        for (int kc = 0; kc < 4; kc++) {
            const int kb = kc * 32;
            uint32_t bfr[8][2];
#pragma unroll
            for (int nt = 0; nt < 8; nt += 2) {
                uint32_t t4[4];
                ldsm4(t4, bB + swz((wn + (nt + (seg >> 1)) * 8 + lrow) * 128 +
                                   kb + (seg & 1) * 16));
                bfr[nt][0] = t4[0]; bfr[nt][1] = t4[1];
                bfr[nt + 1][0] = t4[2]; bfr[nt + 1][1] = t4[3];
            }
#pragma unroll
            for (int mt = 0; mt < 4; mt++) {
                uint32_t af[4];
                ldsm4(af, aA + swz((wm + mt * 16 + (lane & 15)) * 128 +
                                   kb + (lane >> 4) * 16));
#pragma unroll
                for (int nt = 0; nt < 8; nt++)
                    mma16816(acc[mt][nt], af, bfr[nt]);
            }
        }
    }

#pragma unroll
    for (int mt = 0; mt < 4; mt++) {
#pragma unroll
        for (int nt = 0; nt < 8; nt++) {
            int row = bm + wm + mt * 16 + (lane >> 2);
            int col = bn + wn + nt * 8 + (lane & 3) * 2;
            float b0 = bias[col], b1 = bias[col + 1];
            *(float2*)&C[(size_t)row * N + col] =
                make_float2(acc[mt][nt][0] + b0, acc[mt][nt][1] + b1);
            *(float2*)&C[(size_t)(row + 8) * N + col] =
                make_float2(acc[mt][nt][2] + b0, acc[mt][nt][3] + b1);
        }
    }
}

// ---------------- fp32 -> fp16 weights ----------------
__global__ void convB_kernel(const float* __restrict__ s, __half* __restrict__ o, int n4)
{
    int i = blockIdx.x * blockDim.x + threadIdx.x;
    if (i >= n4) return;
    float4 v = ((const float4*)s)[i];
    ((__half2*)o)[2 * i]     = __floats2half2_rn(v.x, v.y);
    ((__half2*)o)[2 * i + 1] = __floats2half2_rn(v.z, v.w);
}

// ---------------- embedding gather ----------------
__global__ __launch_bounds__(256) void embed_kernel(
    const int* __restrict__ caps, const float* __restrict__ Win,
    const float* __restrict__ bin, const float* __restrict__ pos,
    float* __restrict__ x, __half* __restrict__ xh)
{
    int n = blockIdx.x;
    int tok = caps[n];
    int l = n % SEQ;
#pragma unroll
    for (int e = threadIdx.x; e < EDIM; e += 256) {
        float v = Win[(size_t)e * VOC + tok] + bin[e] + pos[l * EDIM + e];
        x[(size_t)n * EDIM + e] = v;
        xh[(size_t)n * EDIM + e] = __float2half_rn(v);
    }
}

// ---------------- causal self-attention: 2 q-halves per (b,h) ----------------
__global__ __launch_bounds__(256) void attn_kernel(const float* __restrict__ qkv,
                                                   __half* __restrict__ out)
{
    int bh = blockIdx.x >> 1, half = blockIdx.x & 1;
    int b = bh >> 3, h = bh & 7;
    const int kmax = half ? 80 : 40;
    __shared__ float Kt[80 * 65];
    __shared__ float Vs[80 * 64];
    __shared__ float pr[8 * 80];
    const float* base = qkv + (size_t)b * SEQ * 3 * EDIM;
    for (int i = threadIdx.x; i < kmax * 64; i += 256) {
        int t = i >> 6, d = i & 63;
        Kt[t * 65 + d] = base[t * 1536 + 512 + h * 64 + d];
        Vs[i]          = base[t * 1536 + 1024 + h * 64 + d];
    }
    __syncthreads();
    int warp = threadIdx.x >> 5, lane = threadIdx.x & 31;
    for (int qi = warp; qi < 40; qi += 8) {
        int q = half * 40 + qi;
        const float* qrow = base + q * 1536 + h * 64;
        int j0 = lane, j1 = lane + 32, j2 = lane + 64;
        const float* k0 = &Kt[j0 * 65];
        const float* k1 = &Kt[(j1 < 80 ? j1 : 0) * 65];
        const float* k2 = &Kt[(j2 < 80 ? j2 : 0) * 65];
        float a0 = 0.f, a1 = 0.f, a2 = 0.f;
#pragma unroll
        for (int kk = 0; kk < 64; kk++) {
            float qv = qrow[kk];
            a0 += qv * k0[kk]; a1 += qv * k1[kk]; a2 += qv * k2[kk];
        }
        float s0 = (j0 <= q) ? a0 * 0.125f : -1e30f;
        float s1 = (j1 <= q) ? a1 * 0.125f : -1e30f;
        float s2 = (j2 <= q) ? a2 * 0.125f : -1e30f;
        float m = fmaxf(fmaxf(s0, s1), s2);
#pragma unroll
        for (int o = 16; o; o >>= 1) m = fmaxf(m, __shfl_xor_sync(0xffffffffu, m, o));
        float p0 = (j0 <= q) ? __expf(s0 - m) : 0.f;
        float p1 = (j1 <= q) ? __expf(s1 - m) : 0.f;
        float p2 = (j2 <= q) ? __expf(s2 - m) : 0.f;
        float sum = p0 + p1 + p2;
#pragma unroll
        for (int o = 16; o; o >>= 1) sum += __shfl_xor_sync(0xffffffffu, sum, o);
        float inv = 1.f / sum;
        pr[warp * 80 + j0] = p0 * inv;
        if (j1 < 80) pr[warp * 80 + j1] = p1 * inv;
        if (j2 < 80) pr[warp * 80 + j2] = p2 * inv;
        __syncwarp();
        float o0 = 0.f, o1 = 0.f;
#pragma unroll 8
        for (int j = 0; j < kmax; j++) {
            float pv = pr[warp * 80 + j];
            o0 += pv * Vs[j * 64 + lane];
            o1 += pv * Vs[j * 64 + 32 + lane];
        }
        out[(size_t)(b * 80 + q) * EDIM + h * 64 + lane] = __float2half_rn(o0);
        out[(size_t)(b * 80 + q) * EDIM + h * 64 + 32 + lane] = __float2half_rn(o1);
        __syncwarp();
    }
}

// ---------------- per-row stats helpers ----------------
__device__ __forceinline__ float2 row_stats(float v0, float v1, float v2, float v3,
                                            float* rs, float* rss, int tid)
{
    float s = v0 + v1 + v2 + v3;
    float ss = v0 * v0 + v1 * v1 + v2 * v2 + v3 * v3;
#pragma unroll
    for (int o = 16; o; o >>= 1) {
        s  += __shfl_xor_sync(0xffffffffu, s, o);
        ss += __shfl_xor_sync(0xffffffffu, ss, o);
    }
    int wid = tid >> 5;
    if ((tid & 31) == 0) { rs[wid] = s; rss[wid] = ss; }
    __syncthreads();
    int base = (tid >> 7) * 4;
    float tots  = rs[base]  + rs[base + 1]  + rs[base + 2]  + rs[base + 3];
    float totss = rss[base] + rss[base + 1] + rss[base + 2] + rss[base + 3];
    float mean = tots * (1.f / 512.f);
    float var = totss * (1.f / 512.f) - mean * mean;
    return make_float2(mean, rsqrtf(var + 1e-5f));
}
__device__ __forceinline__ void st_half4(__half* p, float o0, float o1, float o2, float o3)
{
    __half2 h01 = __floats2half2_rn(o0, o1), h23 = __floats2half2_rn(o2, o3);
    uint2 u;
    u.x = *(uint32_t*)&h01; u.y = *(uint32_t*)&h23;
    *(uint2*)p = u;
}

// ---------------- x = LN(x + a0+a1+a2); vectorized, 2 rows/block ----------------
__global__ __launch_bounds__(256) void add_ln_kernel(
    float* __restrict__ x, __half* __restrict__ xh, const float* __restrict__ add,
    const float* __restrict__ w, const float* __restrict__ b)
{
    __shared__ float rs[8], rss[8];
    int tid = threadIdx.x, tt = tid & 127;
    const size_t P = (size_t)NTOK * EDIM;
    size_t off = (size_t)(blockIdx.x * 2 + (tid >> 7)) * EDIM + tt * 4;
    float4 xv = *(const float4*)&x[off];
    float4 a0 = *(const float4*)&add[off];
    float4 a1 = *(const float4*)&add[P + off];
    float4 a2 = *(const float4*)&add[2 * P + off];
    float v0 = xv.x + a0.x + a1.x + a2.x, v1 = xv.y + a0.y + a1.y + a2.y;
    float v2 = xv.z + a0.z + a1.z + a2.z, v3 = xv.w + a0.w + a1.w + a2.w;
    float2 mi = row_stats(v0, v1, v2, v3, rs, rss, tid);
    int c = tt * 4;
    float4 wv = *(const float4*)&w[c], bv = *(const float4*)&b[c];
    float o0 = (v0 - mi.x) * mi.y * wv.x + bv.x;
    float o1 = (v1 - mi.x) * mi.y * wv.y + bv.y;
    float o2 = (v2 - mi.x) * mi.y * wv.z + bv.z;
    float o3 = (v3 - mi.x) * mi.y * wv.w + bv.w;
    *(float4*)&x[off] = make_float4(o0, o1, o2, o3);
    st_half4(&xh[off], o0, o1, o2, o3);
}

// ---------------- fused ln1 + cvec + ln2; vectorized ----------------
__global__ __launch_bounds__(256) void add_ln2_kernel(
    float* __restrict__ x, __half* __restrict__ xh, const float* __restrict__ add,
    const float* __restrict__ cv,
    const float* __restrict__ w1, const float* __restrict__ b1,
    const float* __restrict__ w2, const float* __restrict__ b2)
{
    __shared__ float rs[8], rss[8];
    int tid = threadIdx.x, tt = tid & 127;
    const size_t P = (size_t)NTOK * EDIM;
    size_t off = (size_t)(blockIdx.x * 2 + (tid >> 7)) * EDIM + tt * 4;
    float4 xv = *(const float4*)&x[off];
    float4 a0 = *(const float4*)&add[off];
    float4 a1 = *(const float4*)&add[P + off];
    float4 a2 = *(const float4*)&add[2 * P + off];
    float v0 = xv.x + a0.x + a1.x + a2.x, v1 = xv.y + a0.y + a1.y + a2.y;
    float v2 = xv.z + a0.z + a1.z + a2.z, v3 = xv.w + a0.w + a1.w + a2.w;
    float2 mi = row_stats(v0, v1, v2, v3, rs, rss, tid);
    int c = tt * 4;
    float4 wv = *(const float4*)&w1[c], bv = *(const float4*)&b1[c];
    float4 cvv = *(const float4*)&cv[c];
    float y0 = (v0 - mi.x) * mi.y * wv.x + bv.x + cvv.x;
    float y1 = (v1 - mi.x) * mi.y * wv.y + bv.y + cvv.y;
    float y2 = (v2 - mi.x) * mi.y * wv.z + bv.z + cvv.z;
    float y3 = (v3 - mi.x) * mi.y * wv.w + bv.w + cvv.w;
    __syncthreads();
    mi = row_stats(y0, y1, y2, y3, rs, rss, tid);
    wv = *(const float4*)&w2[c]; bv = *(const float4*)&b2[c];
    float o0 = (y0 - mi.x) * mi.y * wv.x + bv.x;
    float o1 = (y1 - mi.x) * mi.y * wv.y + bv.y;
    float o2 = (y2 - mi.x) * mi.y * wv.z + bv.z;
    float o3 = (y3 - mi.x) * mi.y * wv.w + bv.w;
    *(float4*)&x[off] = make_float4(o0, o1, o2, o3);
    st_half4(&xh[off], o0, o1, o2, o3);
}

// ---------------- all-layer cross-attn constant vectors ----------------
__global__ void ca_const_kernel(const float* __restrict__ ow, const float* __restrict__ ib,
                                const float* __restrict__ ob, float* __restrict__ c)
{
    int gw = (blockIdx.x * blockDim.x + threadIdx.x) >> 5;
    int lane = threadIdx.x & 31;
    if (gw >= NLAYER * EDIM) return;
    int layer = gw >> 9, e = gw & 511;
    const float* owl = ow + (size_t)layer * EDIM * EDIM + (size_t)e * EDIM;
    const float* vb = ib + (size_t)layer * 3 * EDIM + 2 * EDIM;
    float s = 0.f;
#pragma unroll
    for (int f = lane; f < EDIM; f += 32) s += owl[f] * vb[f];
#pragma unroll
    for (int o = 16; o; o >>= 1) s += __shfl_xor_sync(0xffffffffu, s, o);
    if (lane == 0) c[gw] = ob[gw] + s;
}

// ---------------- launch ----------------
extern "C" void kernel_launch(void* const* d_in, const int* in_sizes, int n_in,
                              void* d_out, int out_size)
{
    const int*   caps    = (const int*)  d_in[0];
    const float* W_in    = (const float*)d_in[1];
    const float* b_in    = (const float*)d_in[2];
    const float* pos_emb = (const float*)d_in[3];
    const float* sa_in_w  = (const float*)d_in[4];
    const float* sa_in_b  = (const float*)d_in[5];
    const float* sa_out_w = (const float*)d_in[6];
    const float* sa_out_b = (const float*)d_in[7];
    const float* ca_in_b  = (const float*)d_in[9];
    const float* ca_out_w = (const float*)d_in[10];
    const float* ca_out_b = (const float*)d_in[11];
    const float* ff1_w = (const float*)d_in[12];
    const float* ff1_b = (const float*)d_in[13];
    const float* ff2_w = (const float*)d_in[14];
    const float* ff2_b = (const float*)d_in[15];
    const float* ln1_w = (const float*)d_in[16];
    const float* ln1_b = (const float*)d_in[17];
    const float* ln2_w = (const float*)d_in[18];
    const float* ln2_b = (const float*)d_in[19];
    const float* ln3_w = (const float*)d_in[20];
    const float* ln3_b = (const float*)d_in[21];
    const float* out_w = (const float*)d_in[22];
    const float* out_b = (const float*)d_in[23];

    float *x, *qkv, *t512, *cvec;
    __half *xh, *t512h, *h1h, *wsain, *wsaout, *wff1, *wff2, *wout;
    cudaGetSymbolAddress((void**)&x, g_x);
    cudaGetSymbolAddress((void**)&qkv, g_qkv);
    cudaGetSymbolAddress((void**)&t512, g_t512);
    cudaGetSymbolAddress((void**)&cvec, g_c);
    cudaGetSymbolAddress((void**)&xh, g_xh);
    cudaGetSymbolAddress((void**)&t512h, g_t512h);
    cudaGetSymbolAddress((void**)&h1h, g_h1h);
    cudaGetSymbolAddress((void**)&wsain, g_wsain);
    cudaGetSymbolAddress((void**)&wsaout, g_wsaout);
    cudaGetSymbolAddress((void**)&wff1, g_wff1);
    cudaGetSymbolAddress((void**)&wff2, g_wff2);
    cudaGetSymbolAddress((void**)&wout, g_wout);

    cudaFuncSetAttribute(gemm_k, cudaFuncAttributeMaxDynamicSharedMemorySize, SMEM_G);
    cudaFuncSetAttribute(gemm_fat, cudaFuncAttributeMaxDynamicSharedMemorySize, SMEM_F);

    cudaStream_t s2;
    cudaStreamCreateWithFlags(&s2, cudaStreamNonBlocking);
    cudaEvent_t eFork, eSain, eCa, eSaout, eFf1, eFf2, eWout;
    cudaEventCreateWithFlags(&eFork, cudaEventDisableTiming);
    cudaEventCreateWithFlags(&eSain, cudaEventDisableTiming);
    cudaEventCreateWithFlags(&eCa, cudaEventDisableTiming);
    cudaEventCreateWithFlags(&eSaout, cudaEventDisableTiming);
    cudaEventCreateWithFlags(&eFf1, cudaEventDisableTiming);
    cudaEventCreateWithFlags(&eFf2, cudaEventDisableTiming);
    cudaEventCreateWithFlags(&eWout, cudaEventDisableTiming);

    auto convOn = [&](cudaStream_t st, const float* src, __half* dst, size_t nelem) {
        int n4 = (int)(nelem / 4);
        convB_kernel<<<(n4 + 255) / 256, 256, 0, st>>>(src, dst, n4);
    };
    auto gemm = [&](const __half* Aw, const __half* Bw, const float* bias,
                    float* C, __half* Ch, int M, int N, int ldk, int ksp, int K,
                    size_t csplit, int relu) {
        int nz = (K + ksp - 1) / ksp;
        gemm_k<<<dim3(M / 128, N / 128, nz), 256, SMEM_G>>>(
            Aw, Bw, bias, C, Ch, M, N, ldk, ksp, K, csplit, relu);
    };

    cudaEventRecord(eFork, 0);
    cudaStreamWaitEvent(s2, eFork, 0);

    embed_kernel<<<NTOK, 256>>>(caps, W_in, b_in, pos_emb, x, xh);
    convOn(s2, sa_in_w, wsain, (size_t)NLAYER * 3 * EDIM * EDIM);
    cudaEventRecord(eSain, s2);
    ca_const_kernel<<<256, 256, 0, s2>>>(ca_out_w, ca_in_b, ca_out_b, cvec);
    cudaEventRecord(eCa, s2);
    convOn(s2, sa_out_w, wsaout, (size_t)NLAYER * EDIM * EDIM);
    cudaEventRecord(eSaout, s2);
    convOn(s2, ff1_w, wff1, (size_t)NLAYER * FFD * EDIM);
    cudaEventRecord(eFf1, s2);

    cudaStreamWaitEvent(0, eSain, 0);
    const size_t CS = (size_t)NTOK * EDIM;
    gemm(xh, wsain, sa_in_b, qkv, nullptr, NTOK, 3 * EDIM, EDIM, EDIM, EDIM, 0, 0);

    convOn(s2, ff2_w, wff2, (size_t)NLAYER * EDIM * FFD);
    cudaEventRecord(eFf2, s2);
    convOn(s2, out_w, wout, (size_t)VOC * EDIM);
    cudaEventRecord(eWout, s2);

    for (int i = 0; i < NLAYER; i++) {
        if (i > 0)
            gemm(xh, wsain + (size_t)i * 3 * EDIM * EDIM, sa_in_b + (size_t)i * 3 * EDIM,
                 qkv, nullptr, NTOK, 3 * EDIM, EDIM, EDIM, EDIM, 0, 0);
        attn_kernel<<<32 * NHEAD * 2, 256>>>(qkv, t512h);
        if (i == 0) cudaStreamWaitEvent(0, eSaout, 0);
        gemm(t512h, wsaout + (size_t)i * EDIM * EDIM, sa_out_b + (size_t)i * EDIM,
             t512, nullptr, NTOK, EDIM, EDIM, 192, EDIM, CS, 0);
        if (i == 0) cudaStreamWaitEvent(0, eCa, 0);
        add_ln2_kernel<<<NTOK / 2, 256>>>(x, xh, t512, cvec + i * EDIM,
                                          ln1_w + i * EDIM, ln1_b + i * EDIM,
                                          ln2_w + i * EDIM, ln2_b + i * EDIM);
        if (i == 0) cudaStreamWaitEvent(0, eFf1, 0);
        gemm(xh, wff1 + (size_t)i * FFD * EDIM, ff1_b + (size_t)i * FFD,
             nullptr, h1h, NTOK, FFD, EDIM, EDIM, EDIM, 0, 1);
        if (i == 0) cudaStreamWaitEvent(0, eFf2, 0);
        gemm(h1h, wff2 + (size_t)i * EDIM * FFD, ff2_b + (size_t)i * EDIM,
             t512, nullptr, NTOK, EDIM, FFD, 704, FFD, CS, 0);
        add_ln_kernel<<<NTOK / 2, 256>>>(x, xh, t512, ln3_w + i * EDIM, ln3_b + i * EDIM);
    }

    cudaStreamWaitEvent(0, eWout, 0);
    // head: fat-tile kernel, 2500 CTAs (16.9 waves)
    gemm_fat<<<dim3(NTOK / FM, VOC / FN), 256, SMEM_F>>>(
        xh, wout, out_b, (float*)d_out, NTOK, VOC, EDIM);
}

// round 11
// speedup vs baseline: 1.0536x; 1.0536x over previous
#include <cuda_runtime.h>
#include <cuda_fp16.h>
#include <cstdint>

#define NTOK 2560
#define EDIM 512
#define NHEAD 8
#define HDIM 64
#define FFD 2048
#define VOC 32000
#define SEQ 80
#define NLAYER 4
#define BK 64

// ---------------- device scratch ----------------
__device__ float g_x[NTOK * EDIM];
__device__ float g_qkv[NTOK * 3 * EDIM];
__device__ float g_t512[3 * NTOK * EDIM];
__device__ float g_c[NLAYER * EDIM];
__device__ __half g_xh[NTOK * EDIM];
__device__ __half g_t512h[NTOK * EDIM];
__device__ __half g_h1h[NTOK * FFD];
__device__ __half g_wsain[NLAYER * 3 * EDIM * EDIM];
__device__ __half g_wsaout[NLAYER * EDIM * EDIM];
__device__ __half g_wff1[NLAYER * FFD * EDIM];
__device__ __half g_wff2[NLAYER * EDIM * FFD];
__device__ __half g_wout[(size_t)VOC * EDIM];

// ---------------- PTX helpers ----------------
__device__ __forceinline__ uint32_t smem_u32(const void* p) {
    uint32_t a;
    asm("{ .reg .u64 t; cvta.to.shared.u64 t, %1; cvt.u32.u64 %0, t; }" : "=r"(a) : "l"(p));
    return a;
}
__device__ __forceinline__ void cp16(uint32_t dst, const void* src) {
    asm volatile("cp.async.cg.shared.global [%0], [%1], 16;\n" :: "r"(dst), "l"(src));
}
__device__ __forceinline__ void cp_commit() { asm volatile("cp.async.commit_group;\n" ::: "memory"); }
template <int N>
__device__ __forceinline__ void cp_wait() { asm volatile("cp.async.wait_group %0;\n" :: "n"(N) : "memory"); }

__device__ __forceinline__ void ldsm4(uint32_t r[4], uint32_t addr) {
    asm volatile("ldmatrix.sync.aligned.m8n8.x4.shared.b16 {%0,%1,%2,%3},[%4];\n"
                 : "=r"(r[0]), "=r"(r[1]), "=r"(r[2]), "=r"(r[3]) : "r"(addr));
}
__device__ __forceinline__ void mma16816(float d[4], const uint32_t a[4], const uint32_t b[2]) {
    asm volatile(
        "mma.sync.aligned.m16n8k16.row.col.f32.f16.f16.f32 "
        "{%0,%1,%2,%3},{%4,%5,%6,%7},{%8,%9},{%0,%1,%2,%3};\n"
        : "+f"(d[0]), "+f"(d[1]), "+f"(d[2]), "+f"(d[3])
        : "r"(a[0]), "r"(a[1]), "r"(a[2]), "r"(a[3]), "r"(b[0]), "r"(b[1]));
}
__device__ __forceinline__ uint32_t swz(uint32_t off) { return off ^ ((off >> 3) & 0x70); }

// ---------------- pipelined fp16 HMMA GEMM, 128x128 CTA, split-K ----
#define BMt 128
#define BNt 128
#define NTN 8
#define NSTG 3
#define STB ((BMt + BNt) * 128)
#define SMEM_G (NSTG * STB)

__global__ void __launch_bounds__(256, 2) gemm_k(
    const __half* __restrict__ A, const __half* __restrict__ B,
    const float* __restrict__ bias, float* __restrict__ C, __half* __restrict__ Ch,
    int M, int N, int ldk, int ksp, int K, size_t csplit, int dorelu)
{
    extern __shared__ __align__(16) char sm[];
    const int tid = threadIdx.x, lane = tid & 31, warp = tid >> 5;
    const int bm = blockIdx.x * BMt, bn = blockIdx.y * BNt;
    const int z = blockIdx.z;
    const int k0 = z * ksp;
    const int klen = min(ksp, K - k0);
    const int S = klen / BK;
    const int wm = (warp & 3) * 32, wn = (warp >> 2) * (NTN * 8);
    const uint32_t smem0 = smem_u32(sm);

    float acc[2][NTN][4] = {};

    auto load_stage = [&](int st, int kabs) {
        uint32_t b0 = smem0 + (uint32_t)st * STB;
#pragma unroll
        for (int i = tid; i < (BMt + BNt) * 8; i += 256) {
            int r = i >> 3, cb = (i & 7) * 16;
            bool isA = r < BMt;
            int rr = isA ? r : r - BMt;
            uint32_t dst = b0 + (isA ? 0u : (uint32_t)BMt * 128) + swz(rr * 128 + cb);
            const char* p = isA ? (const char*)(A + (size_t)(bm + rr) * ldk + kabs) + cb
                                : (const char*)(B + (size_t)(bn + rr) * ldk + kabs) + cb;
            cp16(dst, p);
        }
    };

#pragma unroll
    for (int s = 0; s < NSTG - 1; s++) {
        if (s < S) load_stage(s, k0 + s * BK);
        cp_commit();
    }

    const int lrow = lane & 7, seg = lane >> 3;
    for (int s = 0; s < S; s++) {
        cp_wait<NSTG - 2>();
        __syncthreads();
        if (s + NSTG - 1 < S) load_stage((s + NSTG - 1) % NSTG, k0 + (s + NSTG - 1) * BK);
        cp_commit();

        uint32_t b0 = smem0 + (uint32_t)(s % NSTG) * STB;
        uint32_t aA = b0, bB = b0 + (uint32_t)BMt * 128;

        uint32_t af[2][2][4];
#pragma unroll
        for (int mt = 0; mt < 2; mt++)
            ldsm4(af[0][mt], aA + swz((wm + mt * 16 + (lane & 15)) * 128 + (lane >> 4) * 16));

#pragma unroll
        for (int kc = 0; kc < 4; kc++) {
            const int kb = kc * 32;
            const int cur = kc & 1, nxt = cur ^ 1;
            uint32_t bfr[NTN][2];
#pragma unroll
            for (int nt = 0; nt < NTN; nt += 2) {
                uint32_t t4[4];
                ldsm4(t4, bB + swz((wn + (nt + (seg >> 1)) * 8 + lrow) * 128 +
                                   kb + (seg & 1) * 16));
                bfr[nt][0] = t4[0]; bfr[nt][1] = t4[1];
                bfr[nt + 1][0] = t4[2]; bfr[nt + 1][1] = t4[3];
            }
            if (kc < 3) {
                const int kb2 = kb + 32;
#pragma unroll
                for (int mt = 0; mt < 2; mt++)
                    ldsm4(af[nxt][mt], aA + swz((wm + mt * 16 + (lane & 15)) * 128 +
                                                kb2 + (lane >> 4) * 16));
            }
#pragma unroll
            for (int mt = 0; mt < 2; mt++)
#pragma unroll
                for (int nt = 0; nt < NTN; nt++)
                    mma16816(acc[mt][nt], af[cur][mt], bfr[nt]);
        }
    }

    float* Cz = C ? C + (size_t)z * csplit : nullptr;
#pragma unroll
    for (int mt = 0; mt < 2; mt++) {
#pragma unroll
        for (int nt = 0; nt < NTN; nt++) {
            int row = bm + wm + mt * 16 + (lane >> 2);
            int col = bn + wn + nt * 8 + (lane & 3) * 2;
            float b0 = (z == 0) ? bias[col] : 0.f;
            float b1 = (z == 0) ? bias[col + 1] : 0.f;
            float v0 = acc[mt][nt][0] + b0, v1 = acc[mt][nt][1] + b1;
            float v2 = acc[mt][nt][2] + b0, v3 = acc[mt][nt][3] + b1;
            if (dorelu) {
                v0 = fmaxf(v0, 0.f); v1 = fmaxf(v1, 0.f);
                v2 = fmaxf(v2, 0.f); v3 = fmaxf(v3, 0.f);
            }
            if (Cz) {
                *(float2*)&Cz[(size_t)row * N + col] = make_float2(v0, v1);
                *(float2*)&Cz[(size_t)(row + 8) * N + col] = make_float2(v2, v3);
            }
            if (Ch) {
                *(__half2*)&Ch[(size_t)row * N + col] = __floats2half2_rn(v0, v1);
                *(__half2*)&Ch[(size_t)(row + 8) * N + col] = __floats2half2_rn(v2, v3);
            }
        }
    }
}

// ---------------- fp32 -> fp16 weights ----------------
__global__ void convB_kernel(const float* __restrict__ s, __half* __restrict__ o, int n4)
{
    int i = blockIdx.x * blockDim.x + threadIdx.x;
    if (i >= n4) return;
    float4 v = ((const float4*)s)[i];
    ((__half2*)o)[2 * i]     = __floats2half2_rn(v.x, v.y);
    ((__half2*)o)[2 * i + 1] = __floats2half2_rn(v.z, v.w);
}

// ---------------- embedding gather ----------------
__global__ __launch_bounds__(256) void embed_kernel(
    const int* __restrict__ caps, const float* __restrict__ Win,
    const float* __restrict__ bin, const float* __restrict__ pos,
    float* __restrict__ x, __half* __restrict__ xh)
{
    int n = blockIdx.x;
    int tok = caps[n];
    int l = n % SEQ;
#pragma unroll
    for (int e = threadIdx.x; e < EDIM; e += 256) {
        float v = Win[(size_t)e * VOC + tok] + bin[e] + pos[l * EDIM + e];
        x[(size_t)n * EDIM + e] = v;
        xh[(size_t)n * EDIM + e] = __float2half_rn(v);
    }
}

// ---------------- causal self-attention: 4 q-quarters per (b,h) ----------------
__global__ __launch_bounds__(256) void attn_kernel(const float* __restrict__ qkv,
                                                   __half* __restrict__ out)
{
    int bh = blockIdx.x >> 2, quarter = blockIdx.x & 3;
    int b = bh >> 3, h = bh & 7;
    const int kmax = (quarter + 1) * 20;   // causal: quarter q needs K[0..(q+1)*20)
    __shared__ float Kt[80 * 65];
    __shared__ float Vs[80 * 64];
    __shared__ float pr[8 * 80];
    const float* base = qkv + (size_t)b * SEQ * 3 * EDIM;
    for (int i = threadIdx.x; i < kmax * 64; i += 256) {
        int t = i >> 6, d = i & 63;
        Kt[t * 65 + d] = base[t * 1536 + 512 + h * 64 + d];
        Vs[i]          = base[t * 1536 + 1024 + h * 64 + d];
    }
    __syncthreads();
    int warp = threadIdx.x >> 5, lane = threadIdx.x & 31;
    for (int qi = warp; qi < 20; qi += 8) {
        int q = quarter * 20 + qi;
        const float4* qrow = (const float4*)(base + q * 1536 + h * 64);
        int j0 = lane, j1 = lane + 32, j2 = lane + 64;
        const float* k0 = &Kt[j0 * 65];
        const float* k1 = &Kt[(j1 < 80 ? j1 : 0) * 65];
        const float* k2 = &Kt[(j2 < 80 ? j2 : 0) * 65];
        float a0 = 0.f, a1 = 0.f, a2 = 0.f;
#pragma unroll
        for (int kk = 0; kk < 16; kk++) {
            float4 qv = qrow[kk];     // L1-broadcast vector load
            int kb = kk * 4;
            a0 += qv.x * k0[kb] + qv.y * k0[kb + 1] + qv.z * k0[kb + 2] + qv.w * k0[kb + 3];
            a1 += qv.x * k1[kb] + qv.y * k1[kb + 1] + qv.z * k1[kb + 2] + qv.w * k1[kb + 3];
            a2 += qv.x * k2[kb] + qv.y * k2[kb + 1] + qv.z * k2[kb + 2] + qv.w * k2[kb + 3];
        }
        float s0 = (j0 <= q) ? a0 * 0.125f : -1e30f;
        float s1 = (j1 <= q) ? a1 * 0.125f : -1e30f;
        float s2 = (j2 <= q) ? a2 * 0.125f : -1e30f;
        float m = fmaxf(fmaxf(s0, s1), s2);
#pragma unroll
        for (int o = 16; o; o >>= 1) m = fmaxf(m, __shfl_xor_sync(0xffffffffu, m, o));
        float p0 = (j0 <= q) ? __expf(s0 - m) : 0.f;
        float p1 = (j1 <= q) ? __expf(s1 - m) : 0.f;
        float p2 = (j2 <= q) ? __expf(s2 - m) : 0.f;
        float sum = p0 + p1 + p2;
#pragma unroll
        for (int o = 16; o; o >>= 1) sum += __shfl_xor_sync(0xffffffffu, sum, o);
        float inv = 1.f / sum;
        pr[warp * 80 + j0] = p0 * inv;
        if (j1 < 80) pr[warp * 80 + j1] = p1 * inv;
        if (j2 < 80) pr[warp * 80 + j2] = p2 * inv;
        __syncwarp();
        float o0 = 0.f, o1 = 0.f;
#pragma unroll 10
        for (int j = 0; j < kmax; j++) {   // pr[] is 0 beyond q
            float pv = pr[warp * 80 + j];
            o0 += pv * Vs[j * 64 + lane];
            o1 += pv * Vs[j * 64 + 32 + lane];
        }
        out[(size_t)(b * 80 + q) * EDIM + h * 64 + lane] = __float2half_rn(o0);
        out[(size_t)(b * 80 + q) * EDIM + h * 64 + 32 + lane] = __float2half_rn(o1);
        __syncwarp();
    }
}

// ---------------- per-row stats helpers ----------------
__device__ __forceinline__ float2 row_stats(float v0, float v1, float v2, float v3,
                                            float* rs, float* rss, int tid)
{
    float s = v0 + v1 + v2 + v3;
    float ss = v0 * v0 + v1 * v1 + v2 * v2 + v3 * v3;
#pragma unroll
    for (int o = 16; o; o >>= 1) {
        s  += __shfl_xor_sync(0xffffffffu, s, o);
        ss += __shfl_xor_sync(0xffffffffu, ss, o);
    }
    int wid = tid >> 5;
    if ((tid & 31) == 0) { rs[wid] = s; rss[wid] = ss; }
    __syncthreads();
    int base = (tid >> 7) * 4;
    float tots  = rs[base]  + rs[base + 1]  + rs[base + 2]  + rs[base + 3];
    float totss = rss[base] + rss[base + 1] + rss[base + 2] + rss[base + 3];
    float mean = tots * (1.f / 512.f);
    float var = totss * (1.f / 512.f) - mean * mean;
    return make_float2(mean, rsqrtf(var + 1e-5f));
}
__device__ __forceinline__ void st_half4(__half* p, float o0, float o1, float o2, float o3)
{
    __half2 h01 = __floats2half2_rn(o0, o1), h23 = __floats2half2_rn(o2, o3);
    uint2 u;
    u.x = *(uint32_t*)&h01; u.y = *(uint32_t*)&h23;
    *(uint2*)p = u;
}

// ---------------- x = LN(x + a0+a1+a2); vectorized; optionally skip fp32 write ----
__global__ __launch_bounds__(256) void add_ln_kernel(
    float* __restrict__ x, __half* __restrict__ xh, const float* __restrict__ add,
    const float* __restrict__ w, const float* __restrict__ b, int writeX)
{
    __shared__ float rs[8], rss[8];
    int tid = threadIdx.x, tt = tid & 127;
    const size_t P = (size_t)NTOK * EDIM;
    size_t off = (size_t)(blockIdx.x * 2 + (tid >> 7)) * EDIM + tt * 4;
    float4 xv = *(const float4*)&x[off];
    float4 a0 = *(const float4*)&add[off];
    float4 a1 = *(const float4*)&add[P + off];
    float4 a2 = *(const float4*)&add[2 * P + off];
    float v0 = xv.x + a0.x + a1.x + a2.x, v1 = xv.y + a0.y + a1.y + a2.y;
    float v2 = xv.z + a0.z + a1.z + a2.z, v3 = xv.w + a0.w + a1.w + a2.w;
    float2 mi = row_stats(v0, v1, v2, v3, rs, rss, tid);
    int c = tt * 4;
    float4 wv = *(const float4*)&w[c], bv = *(const float4*)&b[c];
    float o0 = (v0 - mi.x) * mi.y * wv.x + bv.x;
    float o1 = (v1 - mi.x) * mi.y * wv.y + bv.y;
    float o2 = (v2 - mi.x) * mi.y * wv.z + bv.z;
    float o3 = (v3 - mi.x) * mi.y * wv.w + bv.w;
    if (writeX) *(float4*)&x[off] = make_float4(o0, o1, o2, o3);
    st_half4(&xh[off], o0, o1, o2, o3);
}

// ---------------- fused ln1 + cvec + ln2; vectorized ----------------
__global__ __launch_bounds__(256) void add_ln2_kernel(
    float* __restrict__ x, __half* __restrict__ xh, const float* __restrict__ add,
    const float* __restrict__ cv,
    const float* __restrict__ w1, const float* __restrict__ b1,
    const float* __restrict__ w2, const float* __restrict__ b2)
{
    __shared__ float rs[8], rss[8];
    int tid = threadIdx.x, tt = tid & 127;
    const size_t P = (size_t)NTOK * EDIM;
    size_t off = (size_t)(blockIdx.x * 2 + (tid >> 7)) * EDIM + tt * 4;
    float4 xv = *(const float4*)&x[off];
    float4 a0 = *(const float4*)&add[off];
    float4 a1 = *(const float4*)&add[P + off];
    float4 a2 = *(const float4*)&add[2 * P + off];
    float v0 = xv.x + a0.x + a1.x + a2.x, v1 = xv.y + a0.y + a1.y + a2.y;
    float v2 = xv.z + a0.z + a1.z + a2.z, v3 = xv.w + a0.w + a1.w + a2.w;
    float2 mi = row_stats(v0, v1, v2, v3, rs, rss, tid);
    int c = tt * 4;
    float4 wv = *(const float4*)&w1[c], bv = *(const float4*)&b1[c];
    float4 cvv = *(const float4*)&cv[c];
    float y0 = (v0 - mi.x) * mi.y * wv.x + bv.x + cvv.x;
    float y1 = (v1 - mi.x) * mi.y * wv.y + bv.y + cvv.y;
    float y2 = (v2 - mi.x) * mi.y * wv.z + bv.z + cvv.z;
    float y3 = (v3 - mi.x) * mi.y * wv.w + bv.w + cvv.w;
    __syncthreads();
    mi = row_stats(y0, y1, y2, y3, rs, rss, tid);
    wv = *(const float4*)&w2[c]; bv = *(const float4*)&b2[c];
    float o0 = (y0 - mi.x) * mi.y * wv.x + bv.x;
    float o1 = (y1 - mi.x) * mi.y * wv.y + bv.y;
    float o2 = (y2 - mi.x) * mi.y * wv.z + bv.z;
    float o3 = (y3 - mi.x) * mi.y * wv.w + bv.w;
    *(float4*)&x[off] = make_float4(o0, o1, o2, o3);
    st_half4(&xh[off], o0, o1, o2, o3);
}

// ---------------- all-layer cross-attn constant vectors ----------------
__global__ void ca_const_kernel(const float* __restrict__ ow, const float* __restrict__ ib,
                                const float* __restrict__ ob, float* __restrict__ c)
{
    int gw = (blockIdx.x * blockDim.x + threadIdx.x) >> 5;
    int lane = threadIdx.x & 31;
    if (gw >= NLAYER * EDIM) return;
    int layer = gw >> 9, e = gw & 511;
    const float* owl = ow + (size_t)layer * EDIM * EDIM + (size_t)e * EDIM;
    const float* vb = ib + (size_t)layer * 3 * EDIM + 2 * EDIM;
    float s = 0.f;
#pragma unroll
    for (int f = lane; f < EDIM; f += 32) s += owl[f] * vb[f];
#pragma unroll
    for (int o = 16; o; o >>= 1) s += __shfl_xor_sync(0xffffffffu, s, o);
    if (lane == 0) c[gw] = ob[gw] + s;
}

// ---------------- launch ----------------
extern "C" void kernel_launch(void* const* d_in, const int* in_sizes, int n_in,
                              void* d_out, int out_size)
{
    const int*   caps    = (const int*)  d_in[0];
    const float* W_in    = (const float*)d_in[1];
    const float* b_in    = (const float*)d_in[2];
    const float* pos_emb = (const float*)d_in[3];
    const float* sa_in_w  = (const float*)d_in[4];
    const float* sa_in_b  = (const float*)d_in[5];
    const float* sa_out_w = (const float*)d_in[6];
    const float* sa_out_b = (const float*)d_in[7];
    const float* ca_in_b  = (const float*)d_in[9];
    const float* ca_out_w = (const float*)d_in[10];
    const float* ca_out_b = (const float*)d_in[11];
    const float* ff1_w = (const float*)d_in[12];
    const float* ff1_b = (const float*)d_in[13];
    const float* ff2_w = (const float*)d_in[14];
    const float* ff2_b = (const float*)d_in[15];
    const float* ln1_w = (const float*)d_in[16];
    const float* ln1_b = (const float*)d_in[17];
    const float* ln2_w = (const float*)d_in[18];
    const float* ln2_b = (const float*)d_in[19];
    const float* ln3_w = (const float*)d_in[20];
    const float* ln3_b = (const float*)d_in[21];
    const float* out_w = (const float*)d_in[22];
    const float* out_b = (const float*)d_in[23];

    float *x, *qkv, *t512, *cvec;
    __half *xh, *t512h, *h1h, *wsain, *wsaout, *wff1, *wff2, *wout;
    cudaGetSymbolAddress((void**)&x, g_x);
    cudaGetSymbolAddress((void**)&qkv, g_qkv);
    cudaGetSymbolAddress((void**)&t512, g_t512);
    cudaGetSymbolAddress((void**)&cvec, g_c);
    cudaGetSymbolAddress((void**)&xh, g_xh);
    cudaGetSymbolAddress((void**)&t512h, g_t512h);
    cudaGetSymbolAddress((void**)&h1h, g_h1h);
    cudaGetSymbolAddress((void**)&wsain, g_wsain);
    cudaGetSymbolAddress((void**)&wsaout, g_wsaout);
    cudaGetSymbolAddress((void**)&wff1, g_wff1);
    cudaGetSymbolAddress((void**)&wff2, g_wff2);
    cudaGetSymbolAddress((void**)&wout, g_wout);

    cudaFuncSetAttribute(gemm_k, cudaFuncAttributeMaxDynamicSharedMemorySize, SMEM_G);

    cudaStream_t s2;
    cudaStreamCreateWithFlags(&s2, cudaStreamNonBlocking);
    cudaEvent_t eFork, eSain, eCa, eSaout, eFf1, eFf2, eWout;
    cudaEventCreateWithFlags(&eFork, cudaEventDisableTiming);
    cudaEventCreateWithFlags(&eSain, cudaEventDisableTiming);
    cudaEventCreateWithFlags(&eCa, cudaEventDisableTiming);
    cudaEventCreateWithFlags(&eSaout, cudaEventDisableTiming);
    cudaEventCreateWithFlags(&eFf1, cudaEventDisableTiming);
    cudaEventCreateWithFlags(&eFf2, cudaEventDisableTiming);
    cudaEventCreateWithFlags(&eWout, cudaEventDisableTiming);

    auto convOn = [&](cudaStream_t st, const float* src, __half* dst, size_t nelem) {
        int n4 = (int)(nelem / 4);
        convB_kernel<<<(n4 + 255) / 256, 256, 0, st>>>(src, dst, n4);
    };
    auto gemm = [&](const __half* Aw, const __half* Bw, const float* bias,
                    float* C, __half* Ch, int M, int N, int ldk, int ksp, int K,
                    size_t csplit, int relu) {
        int nz = (K + ksp - 1) / ksp;
        gemm_k<<<dim3(M / 128, N / 128, nz), 256, SMEM_G>>>(
            Aw, Bw, bias, C, Ch, M, N, ldk, ksp, K, csplit, relu);
    };

    cudaEventRecord(eFork, 0);
    cudaStreamWaitEvent(s2, eFork, 0);

    embed_kernel<<<NTOK, 256>>>(caps, W_in, b_in, pos_emb, x, xh);
    convOn(s2, sa_in_w, wsain, (size_t)NLAYER * 3 * EDIM * EDIM);
    cudaEventRecord(eSain, s2);
    ca_const_kernel<<<256, 256, 0, s2>>>(ca_out_w, ca_in_b, ca_out_b, cvec);
    cudaEventRecord(eCa, s2);
    convOn(s2, sa_out_w, wsaout, (size_t)NLAYER * EDIM * EDIM);
    cudaEventRecord(eSaout, s2);
    convOn(s2, ff1_w, wff1, (size_t)NLAYER * FFD * EDIM);
    cudaEventRecord(eFf1, s2);

    cudaStreamWaitEvent(0, eSain, 0);
    const size_t CS = (size_t)NTOK * EDIM;
    gemm(xh, wsain, sa_in_b, qkv, nullptr, NTOK, 3 * EDIM, EDIM, EDIM, EDIM, 0, 0);

    convOn(s2, ff2_w, wff2, (size_t)NLAYER * EDIM * FFD);
    cudaEventRecord(eFf2, s2);
    convOn(s2, out_w, wout, (size_t)VOC * EDIM);
    cudaEventRecord(eWout, s2);

    for (int i = 0; i < NLAYER; i++) {
        if (i > 0)
            gemm(xh, wsain + (size_t)i * 3 * EDIM * EDIM, sa_in_b + (size_t)i * 3 * EDIM,
                 qkv, nullptr, NTOK, 3 * EDIM, EDIM, EDIM, EDIM, 0, 0);
        attn_kernel<<<32 * NHEAD * 4, 256>>>(qkv, t512h);
        if (i == 0) cudaStreamWaitEvent(0, eSaout, 0);
        gemm(t512h, wsaout + (size_t)i * EDIM * EDIM, sa_out_b + (size_t)i * EDIM,
             t512, nullptr, NTOK, EDIM, EDIM, 192, EDIM, CS, 0);
        if (i == 0) cudaStreamWaitEvent(0, eCa, 0);
        add_ln2_kernel<<<NTOK / 2, 256>>>(x, xh, t512, cvec + i * EDIM,
                                          ln1_w + i * EDIM, ln1_b + i * EDIM,
                                          ln2_w + i * EDIM, ln2_b + i * EDIM);
        if (i == 0) cudaStreamWaitEvent(0, eFf1, 0);
        gemm(xh, wff1 + (size_t)i * FFD * EDIM, ff1_b + (size_t)i * FFD,
             nullptr, h1h, NTOK, FFD, EDIM, EDIM, EDIM, 0, 1);
        if (i == 0) cudaStreamWaitEvent(0, eFf2, 0);
        gemm(h1h, wff2 + (size_t)i * EDIM * FFD, ff2_b + (size_t)i * EDIM,
             t512, nullptr, NTOK, EDIM, FFD, 704, FFD, CS, 0);
        add_ln_kernel<<<NTOK / 2, 256>>>(x, xh, t512, ln3_w + i * EDIM, ln3_b + i * EDIM,
                                         i < NLAYER - 1);  // last layer: only xh needed
    }

    cudaStreamWaitEvent(0, eWout, 0);
    gemm(xh, wout, out_b, (float*)d_out, nullptr, NTOK, VOC, EDIM, EDIM, EDIM, 0, 0);
}

// round 12
// speedup vs baseline: 1.0556x; 1.0019x over previous
#include <cuda_runtime.h>
#include <cuda_fp16.h>
#include <cstdint>

#define NTOK 2560
#define EDIM 512
#define NHEAD 8
#define HDIM 64
#define FFD 2048
#define VOC 32000
#define SEQ 80
#define NLAYER 4
#define BK 64

// ---------------- device scratch ----------------
__device__ float g_x[NTOK * EDIM];
__device__ float g_qkv[NTOK * 3 * EDIM];
__device__ float g_t512[3 * NTOK * EDIM];
__device__ float g_c[NLAYER * EDIM];
__device__ __half g_xh[NTOK * EDIM];
__device__ __half g_t512h[NTOK * EDIM];
__device__ __half g_h1h[NTOK * FFD];
__device__ __half g_wsain[NLAYER * 3 * EDIM * EDIM];
__device__ __half g_wsaout[NLAYER * EDIM * EDIM];
__device__ __half g_wff1[NLAYER * FFD * EDIM];
__device__ __half g_wff2[NLAYER * EDIM * FFD];
__device__ __half g_wout[(size_t)VOC * EDIM];

// ---------------- PTX helpers ----------------
__device__ __forceinline__ uint32_t smem_u32(const void* p) {
    uint32_t a;
    asm("{ .reg .u64 t; cvta.to.shared.u64 t, %1; cvt.u32.u64 %0, t; }" : "=r"(a) : "l"(p));
    return a;
}
__device__ __forceinline__ void cp16(uint32_t dst, const void* src) {
    asm volatile("cp.async.cg.shared.global [%0], [%1], 16;\n" :: "r"(dst), "l"(src));
}
__device__ __forceinline__ void cp_commit() { asm volatile("cp.async.commit_group;\n" ::: "memory"); }
template <int N>
__device__ __forceinline__ void cp_wait() { asm volatile("cp.async.wait_group %0;\n" :: "n"(N) : "memory"); }

__device__ __forceinline__ void gdc_launch() {
    asm volatile("griddepcontrol.launch_dependents;" ::: "memory");
}
__device__ __forceinline__ void gdc_wait() {
    asm volatile("griddepcontrol.wait;" ::: "memory");
}

__device__ __forceinline__ void ldsm4(uint32_t r[4], uint32_t addr) {
    asm volatile("ldmatrix.sync.aligned.m8n8.x4.shared.b16 {%0,%1,%2,%3},[%4];\n"
                 : "=r"(r[0]), "=r"(r[1]), "=r"(r[2]), "=r"(r[3]) : "r"(addr));
}
__device__ __forceinline__ void mma16816(float d[4], const uint32_t a[4], const uint32_t b[2]) {
    asm volatile(
        "mma.sync.aligned.m16n8k16.row.col.f32.f16.f16.f32 "
        "{%0,%1,%2,%3},{%4,%5,%6,%7},{%8,%9},{%0,%1,%2,%3};\n"
        : "+f"(d[0]), "+f"(d[1]), "+f"(d[2]), "+f"(d[3])
        : "r"(a[0]), "r"(a[1]), "r"(a[2]), "r"(a[3]), "r"(b[0]), "r"(b[1]));
}
__device__ __forceinline__ uint32_t swz(uint32_t off) { return off ^ ((off >> 3) & 0x70); }

// ---------------- pipelined fp16 HMMA GEMM, 128x128 CTA, split-K, PDL ----
#define BMt 128
#define BNt 128
#define NTN 8
#define NSTG 3
#define STB ((BMt + BNt) * 128)
#define SMEM_G (NSTG * STB)

__global__ void __launch_bounds__(256, 2) gemm_k(
    const __half* __restrict__ A, const __half* __restrict__ B,
    const float* __restrict__ bias, float* __restrict__ C, __half* __restrict__ Ch,
    int M, int N, int ldk, int ksp, int K, size_t csplit, int dorelu)
{
    extern __shared__ __align__(16) char sm[];
    const int tid = threadIdx.x, lane = tid & 31, warp = tid >> 5;
    const int bm = blockIdx.x * BMt, bn = blockIdx.y * BNt;
    const int z = blockIdx.z;
    const int k0 = z * ksp;
    const int klen = min(ksp, K - k0);
    const int S = klen / BK;
    const int wm = (warp & 3) * 32, wn = (warp >> 2) * (NTN * 8);
    const uint32_t smem0 = smem_u32(sm);

    float acc[2][NTN][4] = {};

    // trigger dependents ASAP (they spin at their gdc_wait until we complete)
    gdc_launch();

    // prologue part 1: B (weight) tiles — independent of predecessor output
#pragma unroll
    for (int s = 0; s < NSTG - 1; s++) {
        if (s < S) {
            uint32_t b0 = smem0 + (uint32_t)s * STB + (uint32_t)BMt * 128;
            int kabs = k0 + s * BK;
#pragma unroll
            for (int i = tid; i < BNt * 8; i += 256) {
                int r = i >> 3, cb = (i & 7) * 16;
                cp16(b0 + swz(r * 128 + cb),
                     (const char*)(B + (size_t)(bn + r) * ldk + kabs) + cb);
            }
        }
    }

    // predecessor output (A) must be fully visible
    gdc_wait();

    // prologue part 2: A tiles + per-stage commits (g0 = B0..B_{n-1}+A0, g1 = A1, ...)
#pragma unroll
    for (int s = 0; s < NSTG - 1; s++) {
        if (s < S) {
            uint32_t a0 = smem0 + (uint32_t)s * STB;
            int kabs = k0 + s * BK;
#pragma unroll
            for (int i = tid; i < BMt * 8; i += 256) {
                int r = i >> 3, cb = (i & 7) * 16;
                cp16(a0 + swz(r * 128 + cb),
                     (const char*)(A + (size_t)(bm + r) * ldk + kabs) + cb);
            }
        }
        cp_commit();
    }

    auto load_stage = [&](int st, int kabs) {
        uint32_t b0 = smem0 + (uint32_t)st * STB;
#pragma unroll
        for (int i = tid; i < (BMt + BNt) * 8; i += 256) {
            int r = i >> 3, cb = (i & 7) * 16;
            bool isA = r < BMt;
            int rr = isA ? r : r - BMt;
            uint32_t dst = b0 + (isA ? 0u : (uint32_t)BMt * 128) + swz(rr * 128 + cb);
            const char* p = isA ? (const char*)(A + (size_t)(bm + rr) * ldk + kabs) + cb
                                : (const char*)(B + (size_t)(bn + rr) * ldk + kabs) + cb;
            cp16(dst, p);
        }
    };

    const int lrow = lane & 7, seg = lane >> 3;
    for (int s = 0; s < S; s++) {
        cp_wait<NSTG - 2>();
        __syncthreads();
        if (s + NSTG - 1 < S) load_stage((s + NSTG - 1) % NSTG, k0 + (s + NSTG - 1) * BK);
        cp_commit();

        uint32_t b0 = smem0 + (uint32_t)(s % NSTG) * STB;
        uint32_t aA = b0, bB = b0 + (uint32_t)BMt * 128;

        uint32_t af[2][2][4];
#pragma unroll
        for (int mt = 0; mt < 2; mt++)
            ldsm4(af[0][mt], aA + swz((wm + mt * 16 + (lane & 15)) * 128 + (lane >> 4) * 16));

#pragma unroll
        for (int kc = 0; kc < 4; kc++) {
            const int kb = kc * 32;
            const int cur = kc & 1, nxt = cur ^ 1;
            uint32_t bfr[NTN][2];
#pragma unroll
            for (int nt = 0; nt < NTN; nt += 2) {
                uint32_t t4[4];
                ldsm4(t4, bB + swz((wn + (nt + (seg >> 1)) * 8 + lrow) * 128 +
                                   kb + (seg & 1) * 16));
                bfr[nt][0] = t4[0]; bfr[nt][1] = t4[1];
                bfr[nt + 1][0] = t4[2]; bfr[nt + 1][1] = t4[3];
            }
            if (kc < 3) {
                const int kb2 = kb + 32;
#pragma unroll
                for (int mt = 0; mt < 2; mt++)
                    ldsm4(af[nxt][mt], aA + swz((wm + mt * 16 + (lane & 15)) * 128 +
                                                kb2 + (lane >> 4) * 16));
            }
#pragma unroll
            for (int mt = 0; mt < 2; mt++)
#pragma unroll
                for (int nt = 0; nt < NTN; nt++)
                    mma16816(acc[mt][nt], af[cur][mt], bfr[nt]);
        }
    }

    float* Cz = C ? C + (size_t)z * csplit : nullptr;
#pragma unroll
    for (int mt = 0; mt < 2; mt++) {
#pragma unroll
        for (int nt = 0; nt < NTN; nt++) {
            int row = bm + wm + mt * 16 + (lane >> 2);
            int col = bn + wn + nt * 8 + (lane & 3) * 2;
            float b0 = (z == 0) ? bias[col] : 0.f;
            float b1 = (z == 0) ? bias[col + 1] : 0.f;
            float v0 = acc[mt][nt][0] + b0, v1 = acc[mt][nt][1] + b1;
            float v2 = acc[mt][nt][2] + b0, v3 = acc[mt][nt][3] + b1;
            if (dorelu) {
                v0 = fmaxf(v0, 0.f); v1 = fmaxf(v1, 0.f);
                v2 = fmaxf(v2, 0.f); v3 = fmaxf(v3, 0.f);
            }
            if (Cz) {
                *(float2*)&Cz[(size_t)row * N + col] = make_float2(v0, v1);
                *(float2*)&Cz[(size_t)(row + 8) * N + col] = make_float2(v2, v3);
            }
            if (Ch) {
                *(__half2*)&Ch[(size_t)row * N + col] = __floats2half2_rn(v0, v1);
                *(__half2*)&Ch[(size_t)(row + 8) * N + col] = __floats2half2_rn(v2, v3);
            }
        }
    }
}

// ---------------- fp32 -> fp16 weights ----------------
__global__ void convB_kernel(const float* __restrict__ s, __half* __restrict__ o, int n4)
{
    int i = blockIdx.x * blockDim.x + threadIdx.x;
    if (i >= n4) return;
    float4 v = ((const float4*)s)[i];
    ((__half2*)o)[2 * i]     = __floats2half2_rn(v.x, v.y);
    ((__half2*)o)[2 * i + 1] = __floats2half2_rn(v.z, v.w);
}

// ---------------- embedding gather ----------------
__global__ __launch_bounds__(256) void embed_kernel(
    const int* __restrict__ caps, const float* __restrict__ Win,
    const float* __restrict__ bin, const float* __restrict__ pos,
    float* __restrict__ x, __half* __restrict__ xh)
{
    int n = blockIdx.x;
    int tok = caps[n];
    int l = n % SEQ;
#pragma unroll
    for (int e = threadIdx.x; e < EDIM; e += 256) {
        float v = Win[(size_t)e * VOC + tok] + bin[e] + pos[l * EDIM + e];
        x[(size_t)n * EDIM + e] = v;
        xh[(size_t)n * EDIM + e] = __float2half_rn(v);
    }
}

// ---------------- causal self-attention: 4 q-quarters per (b,h), PDL ----------------
__global__ __launch_bounds__(256) void attn_kernel(const float* __restrict__ qkv,
                                                   __half* __restrict__ out)
{
    gdc_launch();
    gdc_wait();
    int bh = blockIdx.x >> 2, quarter = blockIdx.x & 3;
    int b = bh >> 3, h = bh & 7;
    const int kmax = (quarter + 1) * 20;
    __shared__ float Kt[80 * 65];
    __shared__ float Vs[80 * 64];
    __shared__ float pr[8 * 80];
    const float* base = qkv + (size_t)b * SEQ * 3 * EDIM;
    for (int i = threadIdx.x; i < kmax * 64; i += 256) {
        int t = i >> 6, d = i & 63;
        Kt[t * 65 + d] = base[t * 1536 + 512 + h * 64 + d];
        Vs[i]          = base[t * 1536 + 1024 + h * 64 + d];
    }
    __syncthreads();
    int warp = threadIdx.x >> 5, lane = threadIdx.x & 31;
    for (int qi = warp; qi < 20; qi += 8) {
        int q = quarter * 20 + qi;
        const float4* qrow = (const float4*)(base + q * 1536 + h * 64);
        int j0 = lane, j1 = lane + 32, j2 = lane + 64;
        const float* k0 = &Kt[j0 * 65];
        const float* k1 = &Kt[(j1 < 80 ? j1 : 0) * 65];
        const float* k2 = &Kt[(j2 < 80 ? j2 : 0) * 65];
        float a0 = 0.f, a1 = 0.f, a2 = 0.f;
#pragma unroll
        for (int kk = 0; kk < 16; kk++) {
            float4 qv = qrow[kk];
            int kb = kk * 4;
            a0 += qv.x * k0[kb] + qv.y * k0[kb + 1] + qv.z * k0[kb + 2] + qv.w * k0[kb + 3];
            a1 += qv.x * k1[kb] + qv.y * k1[kb + 1] + qv.z * k1[kb + 2] + qv.w * k1[kb + 3];
            a2 += qv.x * k2[kb] + qv.y * k2[kb + 1] + qv.z * k2[kb + 2] + qv.w * k2[kb + 3];
        }
        float s0 = (j0 <= q) ? a0 * 0.125f : -1e30f;
        float s1 = (j1 <= q) ? a1 * 0.125f : -1e30f;
        float s2 = (j2 <= q) ? a2 * 0.125f : -1e30f;
        float m = fmaxf(fmaxf(s0, s1), s2);
#pragma unroll
        for (int o = 16; o; o >>= 1) m = fmaxf(m, __shfl_xor_sync(0xffffffffu, m, o));
        float p0 = (j0 <= q) ? __expf(s0 - m) : 0.f;
        float p1 = (j1 <= q) ? __expf(s1 - m) : 0.f;
        float p2 = (j2 <= q) ? __expf(s2 - m) : 0.f;
        float sum = p0 + p1 + p2;
#pragma unroll
        for (int o = 16; o; o >>= 1) sum += __shfl_xor_sync(0xffffffffu, sum, o);
        float inv = 1.f / sum;
        pr[warp * 80 + j0] = p0 * inv;
        if (j1 < 80) pr[warp * 80 + j1] = p1 * inv;
        if (j2 < 80) pr[warp * 80 + j2] = p2 * inv;
        __syncwarp();
        float o0 = 0.f, o1 = 0.f;
#pragma unroll 10
        for (int j = 0; j < kmax; j++) {
            float pv = pr[warp * 80 + j];
            o0 += pv * Vs[j * 64 + lane];
            o1 += pv * Vs[j * 64 + 32 + lane];
        }
        out[(size_t)(b * 80 + q) * EDIM + h * 64 + lane] = __float2half_rn(o0);
        out[(size_t)(b * 80 + q) * EDIM + h * 64 + 32 + lane] = __float2half_rn(o1);
        __syncwarp();
    }
}

// ---------------- per-row stats helpers ----------------
__device__ __forceinline__ float2 row_stats(float v0, float v1, float v2, float v3,
                                            float* rs, float* rss, int tid)
{
    float s = v0 + v1 + v2 + v3;
    float ss = v0 * v0 + v1 * v1 + v2 * v2 + v3 * v3;
#pragma unroll
    for (int o = 16; o; o >>= 1) {
        s  += __shfl_xor_sync(0xffffffffu, s, o);
        ss += __shfl_xor_sync(0xffffffffu, ss, o);
    }
    int wid = tid >> 5;
    if ((tid & 31) == 0) { rs[wid] = s; rss[wid] = ss; }
    __syncthreads();
    int base = (tid >> 7) * 4;
    float tots  = rs[base]  + rs[base + 1]  + rs[base + 2]  + rs[base + 3];
    float totss = rss[base] + rss[base + 1] + rss[base + 2] + rss[base + 3];
    float mean = tots * (1.f / 512.f);
    float var = totss * (1.f / 512.f) - mean * mean;
    return make_float2(mean, rsqrtf(var + 1e-5f));
}
__device__ __forceinline__ void st_half4(__half* p, float o0, float o1, float o2, float o3)
{
    __half2 h01 = __floats2half2_rn(o0, o1), h23 = __floats2half2_rn(o2, o3);
    uint2 u;
    u.x = *(uint32_t*)&h01; u.y = *(uint32_t*)&h23;
    *(uint2*)p = u;
}

// ---------------- x = LN(x + a0+a1+a2); PDL ----------------
__global__ __launch_bounds__(256) void add_ln_kernel(
    float* __restrict__ x, __half* __restrict__ xh, const float* __restrict__ add,
    const float* __restrict__ w, const float* __restrict__ b, int writeX)
{
    gdc_launch();
    gdc_wait();
    __shared__ float rs[8], rss[8];
    int tid = threadIdx.x, tt = tid & 127;
    const size_t P = (size_t)NTOK * EDIM;
    size_t off = (size_t)(blockIdx.x * 2 + (tid >> 7)) * EDIM + tt * 4;
    float4 xv = *(const float4*)&x[off];
    float4 a0 = *(const float4*)&add[off];
    float4 a1 = *(const float4*)&add[P + off];
    float4 a2 = *(const float4*)&add[2 * P + off];
    float v0 = xv.x + a0.x + a1.x + a2.x, v1 = xv.y + a0.y + a1.y + a2.y;
    float v2 = xv.z + a0.z + a1.z + a2.z, v3 = xv.w + a0.w + a1.w + a2.w;
    float2 mi = row_stats(v0, v1, v2, v3, rs, rss, tid);
    int c = tt * 4;
    float4 wv = *(const float4*)&w[c], bv = *(const float4*)&b[c];
    float o0 = (v0 - mi.x) * mi.y * wv.x + bv.x;
    float o1 = (v1 - mi.x) * mi.y * wv.y + bv.y;
    float o2 = (v2 - mi.x) * mi.y * wv.z + bv.z;
    float o3 = (v3 - mi.x) * mi.y * wv.w + bv.w;
    if (writeX) *(float4*)&x[off] = make_float4(o0, o1, o2, o3);
    st_half4(&xh[off], o0, o1, o2, o3);
}

// ---------------- fused ln1 + cvec + ln2; PDL ----------------
__global__ __launch_bounds__(256) void add_ln2_kernel(
    float* __restrict__ x, __half* __restrict__ xh, const float* __restrict__ add,
    const float* __restrict__ cv,
    const float* __restrict__ w1, const float* __restrict__ b1,
    const float* __restrict__ w2, const float* __restrict__ b2)
{
    gdc_launch();
    gdc_wait();
    __shared__ float rs[8], rss[8];
    int tid = threadIdx.x, tt = tid & 127;
    const size_t P = (size_t)NTOK * EDIM;
    size_t off = (size_t)(blockIdx.x * 2 + (tid >> 7)) * EDIM + tt * 4;
    float4 xv = *(const float4*)&x[off];
    float4 a0 = *(const float4*)&add[off];
    float4 a1 = *(const float4*)&add[P + off];
    float4 a2 = *(const float4*)&add[2 * P + off];
    float v0 = xv.x + a0.x + a1.x + a2.x, v1 = xv.y + a0.y + a1.y + a2.y;
    float v2 = xv.z + a0.z + a1.z + a2.z, v3 = xv.w + a0.w + a1.w + a2.w;
    float2 mi = row_stats(v0, v1, v2, v3, rs, rss, tid);
    int c = tt * 4;
    float4 wv = *(const float4*)&w1[c], bv = *(const float4*)&b1[c];
    float4 cvv = *(const float4*)&cv[c];
    float y0 = (v0 - mi.x) * mi.y * wv.x + bv.x + cvv.x;
    float y1 = (v1 - mi.x) * mi.y * wv.y + bv.y + cvv.y;
    float y2 = (v2 - mi.x) * mi.y * wv.z + bv.z + cvv.z;
    float y3 = (v3 - mi.x) * mi.y * wv.w + bv.w + cvv.w;
    __syncthreads();
    mi = row_stats(y0, y1, y2, y3, rs, rss, tid);
    wv = *(const float4*)&w2[c]; bv = *(const float4*)&b2[c];
    float o0 = (y0 - mi.x) * mi.y * wv.x + bv.x;
    float o1 = (y1 - mi.x) * mi.y * wv.y + bv.y;
    float o2 = (y2 - mi.x) * mi.y * wv.z + bv.z;
    float o3 = (y3 - mi.x) * mi.y * wv.w + bv.w;
    *(float4*)&x[off] = make_float4(o0, o1, o2, o3);
    st_half4(&xh[off], o0, o1, o2, o3);
}

// ---------------- all-layer cross-attn constant vectors ----------------
__global__ void ca_const_kernel(const float* __restrict__ ow, const float* __restrict__ ib,
                                const float* __restrict__ ob, float* __restrict__ c)
{
    int gw = (blockIdx.x * blockDim.x + threadIdx.x) >> 5;
    int lane = threadIdx.x & 31;
    if (gw >= NLAYER * EDIM) return;
    int layer = gw >> 9, e = gw & 511;
    const float* owl = ow + (size_t)layer * EDIM * EDIM + (size_t)e * EDIM;
    const float* vb = ib + (size_t)layer * 3 * EDIM + 2 * EDIM;
    float s = 0.f;
#pragma unroll
    for (int f = lane; f < EDIM; f += 32) s += owl[f] * vb[f];
#pragma unroll
    for (int o = 16; o; o >>= 1) s += __shfl_xor_sync(0xffffffffu, s, o);
    if (lane == 0) c[gw] = ob[gw] + s;
}

// ---------------- PDL launch helper ----------------
template <typename F, typename... Args>
static void launch_pdl(F kern, dim3 grid, dim3 block, size_t smem, Args... args)
{
    cudaLaunchConfig_t cfg = {};
    cfg.gridDim = grid;
    cfg.blockDim = block;
    cfg.dynamicSmemBytes = smem;
    cfg.stream = 0;
    cudaLaunchAttribute attr[1];
    attr[0].id = cudaLaunchAttributeProgrammaticStreamSerialization;
    attr[0].val.programmaticStreamSerializationAllowed = 1;
    cfg.attrs = attr;
    cfg.numAttrs = 1;
    cudaLaunchKernelEx(&cfg, kern, args...);
}

// ---------------- launch ----------------
extern "C" void kernel_launch(void* const* d_in, const int* in_sizes, int n_in,
                              void* d_out, int out_size)
{
    const int*   caps    = (const int*)  d_in[0];
    const float* W_in    = (const float*)d_in[1];
    const float* b_in    = (const float*)d_in[2];
    const float* pos_emb = (const float*)d_in[3];
    const float* sa_in_w  = (const float*)d_in[4];
    const float* sa_in_b  = (const float*)d_in[5];
    const float* sa_out_w = (const float*)d_in[6];
    const float* sa_out_b = (const float*)d_in[7];
    const float* ca_in_b  = (const float*)d_in[9];
    const float* ca_out_w = (const float*)d_in[10];
    const float* ca_out_b = (const float*)d_in[11];
    const float* ff1_w = (const float*)d_in[12];
    const float* ff1_b = (const float*)d_in[13];
    const float* ff2_w = (const float*)d_in[14];
    const float* ff2_b = (const float*)d_in[15];
    const float* ln1_w = (const float*)d_in[16];
    const float* ln1_b = (const float*)d_in[17];
    const float* ln2_w = (const float*)d_in[18];
    const float* ln2_b = (const float*)d_in[19];
    const float* ln3_w = (const float*)d_in[20];
    const float* ln3_b = (const float*)d_in[21];
    const float* out_w = (const float*)d_in[22];
    const float* out_b = (const float*)d_in[23];

    float *x, *qkv, *t512, *cvec;
    __half *xh, *t512h, *h1h, *wsain, *wsaout, *wff1, *wff2, *wout;
    cudaGetSymbolAddress((void**)&x, g_x);
    cudaGetSymbolAddress((void**)&qkv, g_qkv);
    cudaGetSymbolAddress((void**)&t512, g_t512);
    cudaGetSymbolAddress((void**)&cvec, g_c);
    cudaGetSymbolAddress((void**)&xh, g_xh);
    cudaGetSymbolAddress((void**)&t512h, g_t512h);
    cudaGetSymbolAddress((void**)&h1h, g_h1h);
    cudaGetSymbolAddress((void**)&wsain, g_wsain);
    cudaGetSymbolAddress((void**)&wsaout, g_wsaout);
    cudaGetSymbolAddress((void**)&wff1, g_wff1);
    cudaGetSymbolAddress((void**)&wff2, g_wff2);
    cudaGetSymbolAddress((void**)&wout, g_wout);

    cudaFuncSetAttribute(gemm_k, cudaFuncAttributeMaxDynamicSharedMemorySize, SMEM_G);

    cudaStream_t s2;
    cudaStreamCreateWithFlags(&s2, cudaStreamNonBlocking);
    cudaEvent_t eFork, eSain, eCa, eSaout, eFf1, eFf2, eWout;
    cudaEventCreateWithFlags(&eFork, cudaEventDisableTiming);
    cudaEventCreateWithFlags(&eSain, cudaEventDisableTiming);
    cudaEventCreateWithFlags(&eCa, cudaEventDisableTiming);
    cudaEventCreateWithFlags(&eSaout, cudaEventDisableTiming);
    cudaEventCreateWithFlags(&eFf1, cudaEventDisableTiming);
    cudaEventCreateWithFlags(&eFf2, cudaEventDisableTiming);
    cudaEventCreateWithFlags(&eWout, cudaEventDisableTiming);

    auto convOn = [&](cudaStream_t st, const float* src, __half* dst, size_t nelem) {
        int n4 = (int)(nelem / 4);
        convB_kernel<<<(n4 + 255) / 256, 256, 0, st>>>(src, dst, n4);
    };
    auto gemm = [&](const __half* Aw, const __half* Bw, const float* bias,
                    float* C, __half* Ch, int M, int N, int ldk, int ksp, int K,
                    size_t csplit, int relu) {
        int nz = (K + ksp - 1) / ksp;
        launch_pdl(gemm_k, dim3(M / 128, N / 128, nz), dim3(256), (size_t)SMEM_G,
                   Aw, Bw, bias, C, Ch, M, N, ldk, ksp, K, csplit, relu);
    };

    cudaEventRecord(eFork, 0);
    cudaStreamWaitEvent(s2, eFork, 0);

    embed_kernel<<<NTOK, 256>>>(caps, W_in, b_in, pos_emb, x, xh);
    convOn(s2, sa_in_w, wsain, (size_t)NLAYER * 3 * EDIM * EDIM);
    cudaEventRecord(eSain, s2);
    ca_const_kernel<<<256, 256, 0, s2>>>(ca_out_w, ca_in_b, ca_out_b, cvec);
    cudaEventRecord(eCa, s2);
    convOn(s2, sa_out_w, wsaout, (size_t)NLAYER * EDIM * EDIM);
    cudaEventRecord(eSaout, s2);
    convOn(s2, ff1_w, wff1, (size_t)NLAYER * FFD * EDIM);
    cudaEventRecord(eFf1, s2);

    cudaStreamWaitEvent(0, eSain, 0);
    const size_t CS = (size_t)NTOK * EDIM;
    gemm(xh, wsain, sa_in_b, qkv, nullptr, NTOK, 3 * EDIM, EDIM, EDIM, EDIM, 0, 0);

    convOn(s2, ff2_w, wff2, (size_t)NLAYER * EDIM * FFD);
    cudaEventRecord(eFf2, s2);
    convOn(s2, out_w, wout, (size_t)VOC * EDIM);
    cudaEventRecord(eWout, s2);

    for (int i = 0; i < NLAYER; i++) {
        if (i > 0)
            gemm(xh, wsain + (size_t)i * 3 * EDIM * EDIM, sa_in_b + (size_t)i * 3 * EDIM,
                 qkv, nullptr, NTOK, 3 * EDIM, EDIM, EDIM, EDIM, 0, 0);
        launch_pdl(attn_kernel, dim3(32 * NHEAD * 4), dim3(256), (size_t)0,
                   (const float*)qkv, (__half*)t512h);
        if (i == 0) cudaStreamWaitEvent(0, eSaout, 0);
        gemm(t512h, wsaout + (size_t)i * EDIM * EDIM, sa_out_b + (size_t)i * EDIM,
             t512, nullptr, NTOK, EDIM, EDIM, 192, EDIM, CS, 0);
        if (i == 0) cudaStreamWaitEvent(0, eCa, 0);
        launch_pdl(add_ln2_kernel, dim3(NTOK / 2), dim3(256), (size_t)0,
                   x, xh, (const float*)t512, (const float*)(cvec + i * EDIM),
                   ln1_w + i * EDIM, ln1_b + i * EDIM,
                   ln2_w + i * EDIM, ln2_b + i * EDIM);
        if (i == 0) cudaStreamWaitEvent(0, eFf1, 0);
        gemm(xh, wff1 + (size_t)i * FFD * EDIM, ff1_b + (size_t)i * FFD,
             nullptr, h1h, NTOK, FFD, EDIM, EDIM, EDIM, 0, 1);
        if (i == 0) cudaStreamWaitEvent(0, eFf2, 0);
        gemm(h1h, wff2 + (size_t)i * EDIM * FFD, ff2_b + (size_t)i * EDIM,
             t512, nullptr, NTOK, EDIM, FFD, 704, FFD, CS, 0);
        launch_pdl(add_ln_kernel, dim3(NTOK / 2), dim3(256), (size_t)0,
                   x, xh, (const float*)t512,
                   ln3_w + i * EDIM, ln3_b + i * EDIM, (int)(i < NLAYER - 1));
    }

    cudaStreamWaitEvent(0, eWout, 0);
    gemm(xh, wout, out_b, (float*)d_out, nullptr, NTOK, VOC, EDIM, EDIM, EDIM, 0, 0);
}

// round 13
// speedup vs baseline: 1.0580x; 1.0022x over previous
#include <cuda_runtime.h>
#include <cuda_fp16.h>
#include <cstdint>

#define NTOK 2560
#define EDIM 512
#define NHEAD 8
#define HDIM 64
#define FFD 2048
#define VOC 32000
#define SEQ 80
#define NLAYER 4
#define BK 64

// ---------------- device scratch ----------------
__device__ float g_x[NTOK * EDIM];
__device__ float g_qkv[NTOK * 3 * EDIM];
__device__ float g_t512[3 * NTOK * EDIM];
__device__ float g_c[NLAYER * EDIM];
__device__ __half g_xh[NTOK * EDIM];
__device__ __half g_t512h[NTOK * EDIM];
__device__ __half g_h1h[NTOK * FFD];
__device__ __half g_wsain[NLAYER * 3 * EDIM * EDIM];
__device__ __half g_wsaout[NLAYER * EDIM * EDIM];
__device__ __half g_wff1[NLAYER * FFD * EDIM];
__device__ __half g_wff2[NLAYER * EDIM * FFD];
__device__ __half g_wout[(size_t)VOC * EDIM];

// ---------------- PTX helpers ----------------
__device__ __forceinline__ uint32_t smem_u32(const void* p) {
    uint32_t a;
    asm("{ .reg .u64 t; cvta.to.shared.u64 t, %1; cvt.u32.u64 %0, t; }" : "=r"(a) : "l"(p));
    return a;
}
__device__ __forceinline__ void cp16(uint32_t dst, const void* src) {
    asm volatile("cp.async.cg.shared.global [%0], [%1], 16;\n" :: "r"(dst), "l"(src));
}
__device__ __forceinline__ void cp_commit() { asm volatile("cp.async.commit_group;\n" ::: "memory"); }
template <int N>
__device__ __forceinline__ void cp_wait() { asm volatile("cp.async.wait_group %0;\n" :: "n"(N) : "memory"); }

__device__ __forceinline__ void gdc_launch() {
    asm volatile("griddepcontrol.launch_dependents;" ::: "memory");
}
__device__ __forceinline__ void gdc_wait() {
    asm volatile("griddepcontrol.wait;" ::: "memory");
}

__device__ __forceinline__ void ldsm4(uint32_t r[4], uint32_t addr) {
    asm volatile("ldmatrix.sync.aligned.m8n8.x4.shared.b16 {%0,%1,%2,%3},[%4];\n"
                 : "=r"(r[0]), "=r"(r[1]), "=r"(r[2]), "=r"(r[3]) : "r"(addr));
}
__device__ __forceinline__ void mma16816(float d[4], const uint32_t a[4], const uint32_t b[2]) {
    asm volatile(
        "mma.sync.aligned.m16n8k16.row.col.f32.f16.f16.f32 "
        "{%0,%1,%2,%3},{%4,%5,%6,%7},{%8,%9},{%0,%1,%2,%3};\n"
        : "+f"(d[0]), "+f"(d[1]), "+f"(d[2]), "+f"(d[3])
        : "r"(a[0]), "r"(a[1]), "r"(a[2]), "r"(a[3]), "r"(b[0]), "r"(b[1]));
}
__device__ __forceinline__ uint32_t swz(uint32_t off) { return off ^ ((off >> 3) & 0x70); }

// ---------------- pipelined fp16 HMMA GEMM, 128x128 CTA, split-K, PDL ----
#define BMt 128
#define BNt 128
#define NTN 8
#define NSTG 3
#define STB ((BMt + BNt) * 128)
#define SMEM_G (NSTG * STB)

__global__ void __launch_bounds__(256, 2) gemm_k(
    const __half* __restrict__ A, const __half* __restrict__ B,
    const float* __restrict__ bias, float* __restrict__ C, __half* __restrict__ Ch,
    int M, int N, int ldk, int ksp, int K, size_t csplit, int dorelu)
{
    extern __shared__ __align__(16) char sm[];
    const int tid = threadIdx.x, lane = tid & 31, warp = tid >> 5;
    const int bm = blockIdx.x * BMt, bn = blockIdx.y * BNt;
    const int z = blockIdx.z;
    const int k0 = z * ksp;
    const int klen = min(ksp, K - k0);
    const int S = klen / BK;
    const int wm = (warp & 3) * 32, wn = (warp >> 2) * (NTN * 8);
    const uint32_t smem0 = smem_u32(sm);

    float acc[2][NTN][4] = {};

    gdc_launch();

    // prologue part 1: B (weight) tiles — independent of predecessor output
#pragma unroll
    for (int s = 0; s < NSTG - 1; s++) {
        if (s < S) {
            uint32_t b0 = smem0 + (uint32_t)s * STB + (uint32_t)BMt * 128;
            int kabs = k0 + s * BK;
#pragma unroll
            for (int i = tid; i < BNt * 8; i += 256) {
                int r = i >> 3, cb = (i & 7) * 16;
                cp16(b0 + swz(r * 128 + cb),
                     (const char*)(B + (size_t)(bn + r) * ldk + kabs) + cb);
            }
        }
    }

    gdc_wait();

    // prologue part 2: A tiles + per-stage commits
#pragma unroll
    for (int s = 0; s < NSTG - 1; s++) {
        if (s < S) {
            uint32_t a0 = smem0 + (uint32_t)s * STB;
            int kabs = k0 + s * BK;
#pragma unroll
            for (int i = tid; i < BMt * 8; i += 256) {
                int r = i >> 3, cb = (i & 7) * 16;
                cp16(a0 + swz(r * 128 + cb),
                     (const char*)(A + (size_t)(bm + r) * ldk + kabs) + cb);
            }
        }
        cp_commit();
    }

    auto load_stage = [&](int st, int kabs) {
        uint32_t b0 = smem0 + (uint32_t)st * STB;
#pragma unroll
        for (int i = tid; i < (BMt + BNt) * 8; i += 256) {
            int r = i >> 3, cb = (i & 7) * 16;
            bool isA = r < BMt;
            int rr = isA ? r : r - BMt;
            uint32_t dst = b0 + (isA ? 0u : (uint32_t)BMt * 128) + swz(rr * 128 + cb);
            const char* p = isA ? (const char*)(A + (size_t)(bm + rr) * ldk + kabs) + cb
                                : (const char*)(B + (size_t)(bn + rr) * ldk + kabs) + cb;
            cp16(dst, p);
        }
    };

    const int lrow = lane & 7, seg = lane >> 3;
    for (int s = 0; s < S; s++) {
        cp_wait<NSTG - 2>();
        __syncthreads();
        if (s + NSTG - 1 < S) load_stage((s + NSTG - 1) % NSTG, k0 + (s + NSTG - 1) * BK);
        cp_commit();

        uint32_t b0 = smem0 + (uint32_t)(s % NSTG) * STB;
        uint32_t aA = b0, bB = b0 + (uint32_t)BMt * 128;

        uint32_t af[2][2][4];
#pragma unroll
        for (int mt = 0; mt < 2; mt++)
            ldsm4(af[0][mt], aA + swz((wm + mt * 16 + (lane & 15)) * 128 + (lane >> 4) * 16));

#pragma unroll
        for (int kc = 0; kc < 4; kc++) {
            const int kb = kc * 32;
            const int cur = kc & 1, nxt = cur ^ 1;
            uint32_t bfr[NTN][2];
#pragma unroll
            for (int nt = 0; nt < NTN; nt += 2) {
                uint32_t t4[4];
                ldsm4(t4, bB + swz((wn + (nt + (seg >> 1)) * 8 + lrow) * 128 +
                                   kb + (seg & 1) * 16));
                bfr[nt][0] = t4[0]; bfr[nt][1] = t4[1];
                bfr[nt + 1][0] = t4[2]; bfr[nt + 1][1] = t4[3];
            }
            if (kc < 3) {
                const int kb2 = kb + 32;
#pragma unroll
                for (int mt = 0; mt < 2; mt++)
                    ldsm4(af[nxt][mt], aA + swz((wm + mt * 16 + (lane & 15)) * 128 +
                                                kb2 + (lane >> 4) * 16));
            }
#pragma unroll
            for (int mt = 0; mt < 2; mt++)
#pragma unroll
                for (int nt = 0; nt < NTN; nt++)
                    mma16816(acc[mt][nt], af[cur][mt], bfr[nt]);
        }
    }

    float* Cz = C ? C + (size_t)z * csplit : nullptr;
#pragma unroll
    for (int mt = 0; mt < 2; mt++) {
#pragma unroll
        for (int nt = 0; nt < NTN; nt++) {
            int row = bm + wm + mt * 16 + (lane >> 2);
            int col = bn + wn + nt * 8 + (lane & 3) * 2;
            float b0 = (z == 0) ? bias[col] : 0.f;
            float b1 = (z == 0) ? bias[col + 1] : 0.f;
            float v0 = acc[mt][nt][0] + b0, v1 = acc[mt][nt][1] + b1;
            float v2 = acc[mt][nt][2] + b0, v3 = acc[mt][nt][3] + b1;
            if (dorelu) {
                v0 = fmaxf(v0, 0.f); v1 = fmaxf(v1, 0.f);
                v2 = fmaxf(v2, 0.f); v3 = fmaxf(v3, 0.f);
            }
            if (Cz) {
                *(float2*)&Cz[(size_t)row * N + col] = make_float2(v0, v1);
                *(float2*)&Cz[(size_t)(row + 8) * N + col] = make_float2(v2, v3);
            }
            if (Ch) {
                *(__half2*)&Ch[(size_t)row * N + col] = __floats2half2_rn(v0, v1);
                *(__half2*)&Ch[(size_t)(row + 8) * N + col] = __floats2half2_rn(v2, v3);
            }
        }
    }
}

// ---------------- 64x128 GEMM (ff1): finer grid for wave balance, PDL ----------------
#define B2M 64
#define B2N 128
#define STB2 ((B2M + B2N) * 128)
#define SMEM_G2 (NSTG * STB2)

__global__ void __launch_bounds__(256, 2) gemm_k64(
    const __half* __restrict__ A, const __half* __restrict__ B,
    const float* __restrict__ bias, __half* __restrict__ Ch,
    int M, int N, int K, int dorelu)
{
    extern __shared__ __align__(16) char sm[];
    const int tid = threadIdx.x, lane = tid & 31, warp = tid >> 5;
    const int bm = blockIdx.x * B2M, bn = blockIdx.y * B2N;
    const int S = K / BK;
    const int wm = (warp & 1) * 32, wn = (warp >> 1) * 32;   // 2x4 warp grid, 32x32 tiles
    const uint32_t smem0 = smem_u32(sm);

    float acc[2][4][4] = {};

    gdc_launch();

    // prologue: B tiles first (weights, independent), then wait, then A tiles
#pragma unroll
    for (int s = 0; s < NSTG - 1; s++) {
        if (s < S) {
            uint32_t b0 = smem0 + (uint32_t)s * STB2 + (uint32_t)B2M * 128;
            int kabs = s * BK;
#pragma unroll
            for (int i = tid; i < B2N * 8; i += 256) {
                int r = i >> 3, cb = (i & 7) * 16;
                cp16(b0 + swz(r * 128 + cb),
                     (const char*)(B + (size_t)(bn + r) * K + kabs) + cb);
            }
        }
    }
    gdc_wait();
#pragma unroll
    for (int s = 0; s < NSTG - 1; s++) {
        if (s < S) {
            uint32_t a0 = smem0 + (uint32_t)s * STB2;
            int kabs = s * BK;
#pragma unroll
            for (int i = tid; i < B2M * 8; i += 256) {
                int r = i >> 3, cb = (i & 7) * 16;
                cp16(a0 + swz(r * 128 + cb),
                     (const char*)(A + (size_t)(bm + r) * K + kabs) + cb);
            }
        }
        cp_commit();
    }

    auto load_stage = [&](int st, int kabs) {
        uint32_t b0 = smem0 + (uint32_t)st * STB2;
#pragma unroll
        for (int i = tid; i < (B2M + B2N) * 8; i += 256) {
            int r = i >> 3, cb = (i & 7) * 16;
            bool isA = r < B2M;
            int rr = isA ? r : r - B2M;
            uint32_t dst = b0 + (isA ? 0u : (uint32_t)B2M * 128) + swz(rr * 128 + cb);
            const char* p = isA ? (const char*)(A + (size_t)(bm + rr) * K + kabs) + cb
                                : (const char*)(B + (size_t)(bn + rr) * K + kabs) + cb;
            cp16(dst, p);
        }
    };

    const int lrow = lane & 7, seg = lane >> 3;
    for (int s = 0; s < S; s++) {
        cp_wait<NSTG - 2>();
        __syncthreads();
        if (s + NSTG - 1 < S) load_stage((s + NSTG - 1) % NSTG, (s + NSTG - 1) * BK);
        cp_commit();

        uint32_t b0 = smem0 + (uint32_t)(s % NSTG) * STB2;
        uint32_t aA = b0, bB = b0 + (uint32_t)B2M * 128;
#pragma unroll
        for (int kc = 0; kc < 4; kc++) {
            const int kb = kc * 32;
            uint32_t bfr[4][2];
#pragma unroll
            for (int nt = 0; nt < 4; nt += 2) {
                uint32_t t4[4];
                ldsm4(t4, bB + swz((wn + (nt + (seg >> 1)) * 8 + lrow) * 128 +
                                   kb + (seg & 1) * 16));
                bfr[nt][0] = t4[0]; bfr[nt][1] = t4[1];
                bfr[nt + 1][0] = t4[2]; bfr[nt + 1][1] = t4[3];
            }
#pragma unroll
            for (int mt = 0; mt < 2; mt++) {
                uint32_t af[4];
                ldsm4(af, aA + swz((wm + mt * 16 + (lane & 15)) * 128 +
                                   kb + (lane >> 4) * 16));
#pragma unroll
                for (int nt = 0; nt < 4; nt++)
                    mma16816(acc[mt][nt], af, bfr[nt]);
            }
        }
    }

#pragma unroll
    for (int mt = 0; mt < 2; mt++) {
#pragma unroll
        for (int nt = 0; nt < 4; nt++) {
            int row = bm + wm + mt * 16 + (lane >> 2);
            int col = bn + wn + nt * 8 + (lane & 3) * 2;
            float b0 = bias[col], b1 = bias[col + 1];
            float v0 = acc[mt][nt][0] + b0, v1 = acc[mt][nt][1] + b1;
            float v2 = acc[mt][nt][2] + b0, v3 = acc[mt][nt][3] + b1;
            if (dorelu) {
                v0 = fmaxf(v0, 0.f); v1 = fmaxf(v1, 0.f);
                v2 = fmaxf(v2, 0.f); v3 = fmaxf(v3, 0.f);
            }
            *(__half2*)&Ch[(size_t)row * N + col] = __floats2half2_rn(v0, v1);
            *(__half2*)&Ch[(size_t)(row + 8) * N + col] = __floats2half2_rn(v2, v3);
        }
    }
}

// ---------------- fp32 -> fp16 weights ----------------
__global__ void convB_kernel(const float* __restrict__ s, __half* __restrict__ o, int n4)
{
    int i = blockIdx.x * blockDim.x + threadIdx.x;
    if (i >= n4) return;
    float4 v = ((const float4*)s)[i];
    ((__half2*)o)[2 * i]     = __floats2half2_rn(v.x, v.y);
    ((__half2*)o)[2 * i + 1] = __floats2half2_rn(v.z, v.w);
}

// ---------------- embedding gather ----------------
__global__ __launch_bounds__(256) void embed_kernel(
    const int* __restrict__ caps, const float* __restrict__ Win,
    const float* __restrict__ bin, const float* __restrict__ pos,
    float* __restrict__ x, __half* __restrict__ xh)
{
    int n = blockIdx.x;
    int tok = caps[n];
    int l = n % SEQ;
#pragma unroll
    for (int e = threadIdx.x; e < EDIM; e += 256) {
        float v = Win[(size_t)e * VOC + tok] + bin[e] + pos[l * EDIM + e];
        x[(size_t)n * EDIM + e] = v;
        xh[(size_t)n * EDIM + e] = __float2half_rn(v);
    }
}

// ---------------- causal self-attention: 4 q-quarters per (b,h), PDL ----------------
__global__ __launch_bounds__(256) void attn_kernel(const float* __restrict__ qkv,
                                                   __half* __restrict__ out)
{
    gdc_launch();
    gdc_wait();
    int bh = blockIdx.x >> 2, quarter = blockIdx.x & 3;
    int b = bh >> 3, h = bh & 7;
    const int kmax = (quarter + 1) * 20;
    __shared__ float Kt[80 * 65];
    __shared__ float Vs[80 * 64];
    __shared__ float pr[8 * 80];
    const float* base = qkv + (size_t)b * SEQ * 3 * EDIM;
    for (int i = threadIdx.x; i < kmax * 64; i += 256) {
        int t = i >> 6, d = i & 63;
        Kt[t * 65 + d] = base[t * 1536 + 512 + h * 64 + d];
        Vs[i]          = base[t * 1536 + 1024 + h * 64 + d];
    }
    __syncthreads();
    int warp = threadIdx.x >> 5, lane = threadIdx.x & 31;
    for (int qi = warp; qi < 20; qi += 8) {
        int q = quarter * 20 + qi;
        const float4* qrow = (const float4*)(base + q * 1536 + h * 64);
        int j0 = lane, j1 = lane + 32, j2 = lane + 64;
        const float* k0 = &Kt[j0 * 65];
        const float* k1 = &Kt[(j1 < 80 ? j1 : 0) * 65];
        const float* k2 = &Kt[(j2 < 80 ? j2 : 0) * 65];
        float a0 = 0.f, a1 = 0.f, a2 = 0.f;
#pragma unroll
        for (int kk = 0; kk < 16; kk++) {
            float4 qv = qrow[kk];
            int kb = kk * 4;
            a0 += qv.x * k0[kb] + qv.y * k0[kb + 1] + qv.z * k0[kb + 2] + qv.w * k0[kb + 3];
            a1 += qv.x * k1[kb] + qv.y * k1[kb + 1] + qv.z * k1[kb + 2] + qv.w * k1[kb + 3];
            a2 += qv.x * k2[kb] + qv.y * k2[kb + 1] + qv.z * k2[kb + 2] + qv.w * k2[kb + 3];
        }
        float s0 = (j0 <= q) ? a0 * 0.125f : -1e30f;
        float s1 = (j1 <= q) ? a1 * 0.125f : -1e30f;
        float s2 = (j2 <= q) ? a2 * 0.125f : -1e30f;
        float m = fmaxf(fmaxf(s0, s1), s2);
#pragma unroll
        for (int o = 16; o; o >>= 1) m = fmaxf(m, __shfl_xor_sync(0xffffffffu, m, o));
        float p0 = (j0 <= q) ? __expf(s0 - m) : 0.f;
        float p1 = (j1 <= q) ? __expf(s1 - m) : 0.f;
        float p2 = (j2 <= q) ? __expf(s2 - m) : 0.f;
        float sum = p0 + p1 + p2;
#pragma unroll
        for (int o = 16; o; o >>= 1) sum += __shfl_xor_sync(0xffffffffu, sum, o);
        float inv = 1.f / sum;
        pr[warp * 80 + j0] = p0 * inv;
        if (j1 < 80) pr[warp * 80 + j1] = p1 * inv;
        if (j2 < 80) pr[warp * 80 + j2] = p2 * inv;
        __syncwarp();
        float o0 = 0.f, o1 = 0.f;
#pragma unroll 10
        for (int j = 0; j < kmax; j++) {
            float pv = pr[warp * 80 + j];
            o0 += pv * Vs[j * 64 + lane];
            o1 += pv * Vs[j * 64 + 32 + lane];
        }
        out[(size_t)(b * 80 + q) * EDIM + h * 64 + lane] = __float2half_rn(o0);
        out[(size_t)(b * 80 + q) * EDIM + h * 64 + 32 + lane] = __float2half_rn(o1);
        __syncwarp();
    }
}

// ---------------- per-row stats helpers ----------------
__device__ __forceinline__ float2 row_stats(float v0, float v1, float v2, float v3,
                                            float* rs, float* rss, int tid)
{
    float s = v0 + v1 + v2 + v3;
    float ss = v0 * v0 + v1 * v1 + v2 * v2 + v3 * v3;
#pragma unroll
    for (int o = 16; o; o >>= 1) {
        s  += __shfl_xor_sync(0xffffffffu, s, o);
        ss += __shfl_xor_sync(0xffffffffu, ss, o);
    }
    int wid = tid >> 5;
    if ((tid & 31) == 0) { rs[wid] = s; rss[wid] = ss; }
    __syncthreads();
    int base = (tid >> 7) * 4;
    float tots  = rs[base]  + rs[base + 1]  + rs[base + 2]  + rs[base + 3];
    float totss = rss[base] + rss[base + 1] + rss[base + 2] + rss[base + 3];
    float mean = tots * (1.f / 512.f);
    float var = totss * (1.f / 512.f) - mean * mean;
    return make_float2(mean, rsqrtf(var + 1e-5f));
}
__device__ __forceinline__ void st_half4(__half* p, float o0, float o1, float o2, float o3)
{
    __half2 h01 = __floats2half2_rn(o0, o1), h23 = __floats2half2_rn(o2, o3);
    uint2 u;
    u.x = *(uint32_t*)&h01; u.y = *(uint32_t*)&h23;
    *(uint2*)p = u;
}

// ---------------- x = LN(x + a0+a1+a2); PDL ----------------
__global__ __launch_bounds__(256) void add_ln_kernel(
    float* __restrict__ x, __half* __restrict__ xh, const float* __restrict__ add,
    const float* __restrict__ w, const float* __restrict__ b, int writeX)
{
    gdc_launch();
    gdc_wait();
    __shared__ float rs[8], rss[8];
    int tid = threadIdx.x, tt = tid & 127;
    const size_t P = (size_t)NTOK * EDIM;
    size_t off = (size_t)(blockIdx.x * 2 + (tid >> 7)) * EDIM + tt * 4;
    float4 xv = *(const float4*)&x[off];
    float4 a0 = *(const float4*)&add[off];
    float4 a1 = *(const float4*)&add[P + off];
    float4 a2 = *(const float4*)&add[2 * P + off];
    float v0 = xv.x + a0.x + a1.x + a2.x, v1 = xv.y + a0.y + a1.y + a2.y;
    float v2 = xv.z + a0.z + a1.z + a2.z, v3 = xv.w + a0.w + a1.w + a2.w;
    float2 mi = row_stats(v0, v1, v2, v3, rs, rss, tid);
    int c = tt * 4;
    float4 wv = *(const float4*)&w[c], bv = *(const float4*)&b[c];
    float o0 = (v0 - mi.x) * mi.y * wv.x + bv.x;
    float o1 = (v1 - mi.x) * mi.y * wv.y + bv.y;
    float o2 = (v2 - mi.x) * mi.y * wv.z + bv.z;
    float o3 = (v3 - mi.x) * mi.y * wv.w + bv.w;
    if (writeX) *(float4*)&x[off] = make_float4(o0, o1, o2, o3);
    st_half4(&xh[off], o0, o1, o2, o3);
}

// ---------------- fused ln1 + cvec + ln2; PDL ----------------
__global__ __launch_bounds__(256) void add_ln2_kernel(
    float* __restrict__ x, __half* __restrict__ xh, const float* __restrict__ add,
    const float* __restrict__ cv,
    const float* __restrict__ w1, const float* __restrict__ b1,
    const float* __restrict__ w2, const float* __restrict__ b2)
{
    gdc_launch();
    gdc_wait();
    __shared__ float rs[8], rss[8];
    int tid = threadIdx.x, tt = tid & 127;
    const size_t P = (size_t)NTOK * EDIM;
    size_t off = (size_t)(blockIdx.x * 2 + (tid >> 7)) * EDIM + tt * 4;
    float4 xv = *(const float4*)&x[off];
    float4 a0 = *(const float4*)&add[off];
    float4 a1 = *(const float4*)&add[P + off];
    float4 a2 = *(const float4*)&add[2 * P + off];
    float v0 = xv.x + a0.x + a1.x + a2.x, v1 = xv.y + a0.y + a1.y + a2.y;
    float v2 = xv.z + a0.z + a1.z + a2.z, v3 = xv.w + a0.w + a1.w + a2.w;
    float2 mi = row_stats(v0, v1, v2, v3, rs, rss, tid);
    int c = tt * 4;
    float4 wv = *(const float4*)&w1[c], bv = *(const float4*)&b1[c];
    float4 cvv = *(const float4*)&cv[c];
    float y0 = (v0 - mi.x) * mi.y * wv.x + bv.x + cvv.x;
    float y1 = (v1 - mi.x) * mi.y * wv.y + bv.y + cvv.y;
    float y2 = (v2 - mi.x) * mi.y * wv.z + bv.z + cvv.z;
    float y3 = (v3 - mi.x) * mi.y * wv.w + bv.w + cvv.w;
    __syncthreads();
    mi = row_stats(y0, y1, y2, y3, rs, rss, tid);
    wv = *(const float4*)&w2[c]; bv = *(const float4*)&b2[c];
    float o0 = (y0 - mi.x) * mi.y * wv.x + bv.x;
    float o1 = (y1 - mi.x) * mi.y * wv.y + bv.y;
    float o2 = (y2 - mi.x) * mi.y * wv.z + bv.z;
    float o3 = (y3 - mi.x) * mi.y * wv.w + bv.w;
    *(float4*)&x[off] = make_float4(o0, o1, o2, o3);
    st_half4(&xh[off], o0, o1, o2, o3);
}

// ---------------- all-layer cross-attn constant vectors ----------------
__global__ void ca_const_kernel(const float* __restrict__ ow, const float* __restrict__ ib,
                                const float* __restrict__ ob, float* __restrict__ c)
{
    int gw = (blockIdx.x * blockDim.x + threadIdx.x) >> 5;
    int lane = threadIdx.x & 31;
    if (gw >= NLAYER * EDIM) return;
    int layer = gw >> 9, e = gw & 511;
    const float* owl = ow + (size_t)layer * EDIM * EDIM + (size_t)e * EDIM;
    const float* vb = ib + (size_t)layer * 3 * EDIM + 2 * EDIM;
    float s = 0.f;
#pragma unroll
    for (int f = lane; f < EDIM; f += 32) s += owl[f] * vb[f];
#pragma unroll
    for (int o = 16; o; o >>= 1) s += __shfl_xor_sync(0xffffffffu, s, o);
    if (lane == 0) c[gw] = ob[gw] + s;
}

// ---------------- PDL launch helper ----------------
template <typename F, typename... Args>
static void launch_pdl(F kern, dim3 grid, dim3 block, size_t smem, Args... args)
{
    cudaLaunchConfig_t cfg = {};
    cfg.gridDim = grid;
    cfg.blockDim = block;
    cfg.dynamicSmemBytes = smem;
    cfg.stream = 0;
    cudaLaunchAttribute attr[1];
    attr[0].id = cudaLaunchAttributeProgrammaticStreamSerialization;
    attr[0].val.programmaticStreamSerializationAllowed = 1;
    cfg.attrs = attr;
    cfg.numAttrs = 1;
    cudaLaunchKernelEx(&cfg, kern, args...);
}

// ---------------- launch ----------------
extern "C" void kernel_launch(void* const* d_in, const int* in_sizes, int n_in,
                              void* d_out, int out_size)
{
    const int*   caps    = (const int*)  d_in[0];
    const float* W_in    = (const float*)d_in[1];
    const float* b_in    = (const float*)d_in[2];
    const float* pos_emb = (const float*)d_in[3];
    const float* sa_in_w  = (const float*)d_in[4];
    const float* sa_in_b  = (const float*)d_in[5];
    const float* sa_out_w = (const float*)d_in[6];
    const float* sa_out_b = (const float*)d_in[7];
    const float* ca_in_b  = (const float*)d_in[9];
    const float* ca_out_w = (const float*)d_in[10];
    const float* ca_out_b = (const float*)d_in[11];
    const float* ff1_w = (const float*)d_in[12];
    const float* ff1_b = (const float*)d_in[13];
    const float* ff2_w = (const float*)d_in[14];
    const float* ff2_b = (const float*)d_in[15];
    const float* ln1_w = (const float*)d_in[16];
    const float* ln1_b = (const float*)d_in[17];
    const float* ln2_w = (const float*)d_in[18];
    const float* ln2_b = (const float*)d_in[19];
    const float* ln3_w = (const float*)d_in[20];
    const float* ln3_b = (const float*)d_in[21];
    const float* out_w = (const float*)d_in[22];
    const float* out_b = (const float*)d_in[23];

    float *x, *qkv, *t512, *cvec;
    __half *xh, *t512h, *h1h, *wsain, *wsaout, *wff1, *wff2, *wout;
    cudaGetSymbolAddress((void**)&x, g_x);
    cudaGetSymbolAddress((void**)&qkv, g_qkv);
    cudaGetSymbolAddress((void**)&t512, g_t512);
    cudaGetSymbolAddress((void**)&cvec, g_c);
    cudaGetSymbolAddress((void**)&xh, g_xh);
    cudaGetSymbolAddress((void**)&t512h, g_t512h);
    cudaGetSymbolAddress((void**)&h1h, g_h1h);
    cudaGetSymbolAddress((void**)&wsain, g_wsain);
    cudaGetSymbolAddress((void**)&wsaout, g_wsaout);
    cudaGetSymbolAddress((void**)&wff1, g_wff1);
    cudaGetSymbolAddress((void**)&wff2, g_wff2);
    cudaGetSymbolAddress((void**)&wout, g_wout);

    cudaFuncSetAttribute(gemm_k, cudaFuncAttributeMaxDynamicSharedMemorySize, SMEM_G);
    cudaFuncSetAttribute(gemm_k64, cudaFuncAttributeMaxDynamicSharedMemorySize, SMEM_G2);

    cudaStream_t s2;
    cudaStreamCreateWithFlags(&s2, cudaStreamNonBlocking);
    cudaEvent_t eFork, eSain, eCa, eSaout, eFf1, eFf2, eWout;
    cudaEventCreateWithFlags(&eFork, cudaEventDisableTiming);
    cudaEventCreateWithFlags(&eSain, cudaEventDisableTiming);
    cudaEventCreateWithFlags(&eCa, cudaEventDisableTiming);
    cudaEventCreateWithFlags(&eSaout, cudaEventDisableTiming);
    cudaEventCreateWithFlags(&eFf1, cudaEventDisableTiming);
    cudaEventCreateWithFlags(&eFf2, cudaEventDisableTiming);
    cudaEventCreateWithFlags(&eWout, cudaEventDisableTiming);

    auto convOn = [&](cudaStream_t st, const float* src, __half* dst, size_t nelem) {
        int n4 = (int)(nelem / 4);
        convB_kernel<<<(n4 + 255) / 256, 256, 0, st>>>(src, dst, n4);
    };
    auto gemm = [&](const __half* Aw, const __half* Bw, const float* bias,
                    float* C, __half* Ch, int M, int N, int ldk, int ksp, int K,
                    size_t csplit, int relu) {
        int nz = (K + ksp - 1) / ksp;
        launch_pdl(gemm_k, dim3(M / 128, N / 128, nz), dim3(256), (size_t)SMEM_G,
                   Aw, Bw, bias, C, Ch, M, N, ldk, ksp, K, csplit, relu);
    };

    cudaEventRecord(eFork, 0);
    cudaStreamWaitEvent(s2, eFork, 0);

    embed_kernel<<<NTOK, 256>>>(caps, W_in, b_in, pos_emb, x, xh);
    convOn(s2, sa_in_w, wsain, (size_t)NLAYER * 3 * EDIM * EDIM);
    cudaEventRecord(eSain, s2);
    ca_const_kernel<<<256, 256, 0, s2>>>(ca_out_w, ca_in_b, ca_out_b, cvec);
    cudaEventRecord(eCa, s2);
    convOn(s2, sa_out_w, wsaout, (size_t)NLAYER * EDIM * EDIM);
    cudaEventRecord(eSaout, s2);
    convOn(s2, ff1_w, wff1, (size_t)NLAYER * FFD * EDIM);
    cudaEventRecord(eFf1, s2);

    cudaStreamWaitEvent(0, eSain, 0);
    const size_t CS = (size_t)NTOK * EDIM;
    gemm(xh, wsain, sa_in_b, qkv, nullptr, NTOK, 3 * EDIM, EDIM, EDIM, EDIM, 0, 0);

    convOn(s2, ff2_w, wff2, (size_t)NLAYER * EDIM * FFD);
    cudaEventRecord(eFf2, s2);
    convOn(s2, out_w, wout, (size_t)VOC * EDIM);
    cudaEventRecord(eWout, s2);

    for (int i = 0; i < NLAYER; i++) {
        if (i > 0)
            gemm(xh, wsain + (size_t)i * 3 * EDIM * EDIM, sa_in_b + (size_t)i * 3 * EDIM,
                 qkv, nullptr, NTOK, 3 * EDIM, EDIM, EDIM, EDIM, 0, 0);
        launch_pdl(attn_kernel, dim3(32 * NHEAD * 4), dim3(256), (size_t)0,
                   (const float*)qkv, (__half*)t512h);
        if (i == 0) cudaStreamWaitEvent(0, eSaout, 0);
        gemm(t512h, wsaout + (size_t)i * EDIM * EDIM, sa_out_b + (size_t)i * EDIM,
             t512, nullptr, NTOK, EDIM, EDIM, 192, EDIM, CS, 0);
        if (i == 0) cudaStreamWaitEvent(0, eCa, 0);
        launch_pdl(add_ln2_kernel, dim3(NTOK / 2), dim3(256), (size_t)0,
                   x, xh, (const float*)t512, (const float*)(cvec + i * EDIM),
                   ln1_w + i * EDIM, ln1_b + i * EDIM,
                   ln2_w + i * EDIM, ln2_b + i * EDIM);
        if (i == 0) cudaStreamWaitEvent(0, eFf1, 0);
        // ff1: 64x128 tile -> grid 40x16 = 640 CTAs (better per-SM work granularity)
        launch_pdl(gemm_k64, dim3(NTOK / B2M, FFD / B2N), dim3(256), (size_t)SMEM_G2,
                   (const __half*)xh, (const __half*)(wff1 + (size_t)i * FFD * EDIM),
                   ff1_b + (size_t)i * FFD, h1h, NTOK, FFD, EDIM, 1);
        if (i == 0) cudaStreamWaitEvent(0, eFf2, 0);
        gemm(h1h, wff2 + (size_t)i * EDIM * FFD, ff2_b + (size_t)i * EDIM,
             t512, nullptr, NTOK, EDIM, FFD, 704, FFD, CS, 0);
        launch_pdl(add_ln_kernel, dim3(NTOK / 2), dim3(256), (size_t)0,
                   x, xh, (const float*)t512,
                   ln3_w + i * EDIM, ln3_b + i * EDIM, (int)(i < NLAYER - 1));
    }

    cudaStreamWaitEvent(0, eWout, 0);
    gemm(xh, wout, out_b, (float*)d_out, nullptr, NTOK, VOC, EDIM, EDIM, EDIM, 0, 0);
}